// round 5
// baseline (speedup 1.0000x reference)
#include <cuda_runtime.h>
#include <cuda_bf16.h>

// Problem constants
#define BB    4
#define HDIM  56
#define WDIM  56
#define CC    256
#define NW    7
#define WS    8
#define P2    49
#define PIX   64
#define NHEAD 8
#define HDH   32
#define TOPK  4
#define MTOT  (BB * P2 * PIX)      // 12544 == BB*HDIM*WDIM
#define QKVW  768
#define SCALE 0.0625f              // 256^-0.5

// Scratch (window-ordered where noted)
__device__ float g_qkv[(size_t)MTOT * QKVW];       // (b,p,pix, 768): q|k|v
__device__ float g_qwin[BB * P2 * CC];
__device__ float g_kwin[BB * P2 * CC];
__device__ int   g_ridx[BB * P2 * TOPK];
__device__ float g_lepe[(size_t)BB * HDIM * WDIM * CC];   // image layout
__device__ float g_aout[(size_t)MTOT * CC];               // window layout

// ---------------------------------------------------------------------------
// Kernel 1: QKV GEMM  (M=12544 window-ordered rows, K=256, N=768)
// ---------------------------------------------------------------------------
__global__ __launch_bounds__(256) void gemm_qkv_kernel(
    const float* __restrict__ x, const float* __restrict__ Wqkv,
    const float* __restrict__ bqkv)
{
    __shared__ float as[8][128];
    __shared__ float bs[8][128];
    int t = threadIdx.x;
    int tx = t & 15, ty = t >> 4;
    int m0 = blockIdx.x * 128;
    int n0 = blockIdx.y * 128;

    // A-load assignment: one float4 per thread per k-step
    int arow = t >> 1;
    int aq   = (t & 1) * 4;
    int m = m0 + arow;
    int b = m / 3136, r2 = m % 3136;
    int p = r2 >> 6, pix = r2 & 63;
    int y  = (p / NW) * WS + (pix >> 3);
    int xx = (p % NW) * WS + (pix & 7);
    const float* aptr = x + (size_t)(b * 3136 + y * WDIM + xx) * CC;

    int brow = t >> 5;
    int bq   = (t & 31) * 4;

    float acc[8][8];
#pragma unroll
    for (int i = 0; i < 8; i++)
#pragma unroll
        for (int j = 0; j < 8; j++) acc[i][j] = 0.f;

    for (int k0 = 0; k0 < CC; k0 += 8) {
        float4 av = *(const float4*)(aptr + k0 + aq);
        float4 bv = *(const float4*)(Wqkv + (size_t)(k0 + brow) * QKVW + n0 + bq);
        as[aq + 0][arow] = av.x;
        as[aq + 1][arow] = av.y;
        as[aq + 2][arow] = av.z;
        as[aq + 3][arow] = av.w;
        *(float4*)&bs[brow][bq] = bv;
        __syncthreads();
#pragma unroll
        for (int kk = 0; kk < 8; kk++) {
            float4 a0 = *(float4*)&as[kk][ty * 8];
            float4 a1 = *(float4*)&as[kk][ty * 8 + 4];
            float4 b0 = *(float4*)&bs[kk][tx * 8];
            float4 b1 = *(float4*)&bs[kk][tx * 8 + 4];
            float ra[8] = {a0.x, a0.y, a0.z, a0.w, a1.x, a1.y, a1.z, a1.w};
            float rb[8] = {b0.x, b0.y, b0.z, b0.w, b1.x, b1.y, b1.z, b1.w};
#pragma unroll
            for (int i = 0; i < 8; i++)
#pragma unroll
                for (int j = 0; j < 8; j++) acc[i][j] += ra[i] * rb[j];
        }
        __syncthreads();
    }
#pragma unroll
    for (int i = 0; i < 8; i++) {
        int mm = m0 + ty * 8 + i;
        float* orow = g_qkv + (size_t)mm * QKVW + n0 + tx * 8;
#pragma unroll
        for (int j = 0; j < 8; j++) orow[j] = acc[i][j] + bqkv[n0 + tx * 8 + j];
    }
}

// ---------------------------------------------------------------------------
// Kernel 2: per-window means of q and k
// ---------------------------------------------------------------------------
__global__ void win_mean_kernel()
{
    int bp = blockIdx.x;            // 0..195
    int c = threadIdx.x;            // 0..255
    const float* base = g_qkv + (size_t)bp * PIX * QKVW;
    float sq = 0.f, sk = 0.f;
#pragma unroll 4
    for (int px = 0; px < PIX; px++) {
        sq += base[px * QKVW + c];
        sk += base[px * QKVW + CC + c];
    }
    g_qwin[bp * CC + c] = sq * (1.f / 64.f);
    g_kwin[bp * CC + c] = sk * (1.f / 64.f);
}

// ---------------------------------------------------------------------------
// Kernel 3: routing logits + top-4 (set is permutation-invariant downstream)
// ---------------------------------------------------------------------------
__global__ void routing_kernel()
{
    __shared__ float lg[P2];
    int b = blockIdx.x / P2;
    int p = blockIdx.x % P2;
    int t = threadIdx.x;
    if (t < P2) {
        const float* qr = g_qwin + (size_t)(b * P2 + p) * CC;
        const float* kr = g_kwin + (size_t)(b * P2 + t) * CC;
        float s = 0.f;
        for (int c = 0; c < CC; c++) s += qr[c] * kr[c];
        lg[t] = s;
    }
    __syncthreads();
    if (t == 0) {
        for (int s = 0; s < TOPK; s++) {
            float best = -1e30f; int bi = 0;
            for (int j = 0; j < P2; j++)
                if (lg[j] > best) { best = lg[j]; bi = j; }
            g_ridx[(b * P2 + p) * TOPK + s] = bi;
            lg[bi] = -1e30f;
        }
    }
}

// ---------------------------------------------------------------------------
// Kernel 4: lepe = depthwise 5x5 conv over v (read from window layout)
// ---------------------------------------------------------------------------
__global__ void lepe_kernel(const float* __restrict__ lw,
                            const float* __restrict__ lb)
{
    int idx = blockIdx.x * 256 + threadIdx.x;
    int c = idx & 255;
    int r = idx >> 8;
    int xx = r % WDIM; r /= WDIM;
    int y = r % HDIM;
    int b = r / HDIM;
    float acc = lb[c];
#pragma unroll
    for (int dy = 0; dy < 5; dy++) {
        int yy = y + dy - 2;
        if (yy < 0 || yy >= HDIM) continue;
#pragma unroll
        for (int dx = 0; dx < 5; dx++) {
            int xs = xx + dx - 2;
            if (xs < 0 || xs >= WDIM) continue;
            int p = (yy >> 3) * NW + (xs >> 3);
            int px = ((yy & 7) << 3) + (xs & 7);
            float v = g_qkv[(size_t)((b * P2 + p) * PIX + px) * QKVW + 2 * CC + c];
            acc += v * lw[(dy * 5 + dx) * CC + c];
        }
    }
    g_lepe[idx] = acc;
}

// ---------------------------------------------------------------------------
// Kernel 5: attention per (b, window, head).
// smem: q[64x32], v[256 x 36(pad)], scores[64 x 257(pad)], partials.
// k rows live in registers (one key per thread).
// ---------------------------------------------------------------------------
#define SM_Q   0
#define SM_V   2048
#define SM_SC  (2048 + 256 * 36)                 // 11264
#define SM_PM  (SM_SC + 64 * 257)                // 27712
#define SM_PS  (SM_PM + 256)                     // 27968
#define SM_FLOATS (SM_PS + 256)                  // 28224 -> 112896 B

__global__ __launch_bounds__(256) void attn_kernel()
{
    extern __shared__ float sm[];
    float* q_s  = sm + SM_Q;
    float* v_s  = sm + SM_V;
    float* sc   = sm + SM_SC;
    float* pmax = sm + SM_PM;
    float* psum = sm + SM_PS;

    int blk = blockIdx.x;
    int b  = blk / (P2 * NHEAD);
    int p  = (blk / NHEAD) % P2;
    int hh = blk % NHEAD;
    int bp = b * P2 + p;
    int t = threadIdx.x;

    int widx[TOPK];
#pragma unroll
    for (int s = 0; s < TOPK; s++) widx[s] = g_ridx[bp * TOPK + s];

    // load q (scaled) : 512 float4, 2 per thread
#pragma unroll
    for (int i = 0; i < 2; i++) {
        int f = t + i * 256;
        int px = f >> 3, q4 = (f & 7) * 4;
        float4 v = *(const float4*)(g_qkv + (size_t)(bp * PIX + px) * QKVW + hh * HDH + q4);
        float4 o; o.x = v.x * SCALE; o.y = v.y * SCALE; o.z = v.z * SCALE; o.w = v.w * SCALE;
        *(float4*)&q_s[px * HDH + q4] = o;
    }

    // load v tile into padded smem: 2048 float4, 8 per thread
#pragma unroll
    for (int i = 0; i < 8; i++) {
        int f = t + i * 256;
        int row = f >> 3, q4 = (f & 7) * 4;
        int s = row >> 6, loc = row & 63;
        float4 v = *(const float4*)(g_qkv +
            (size_t)((b * P2 + widx[s]) * PIX + loc) * QKVW + 2 * CC + hh * HDH + q4);
        v_s[row * 36 + q4 + 0] = v.x;
        v_s[row * 36 + q4 + 1] = v.y;
        v_s[row * 36 + q4 + 2] = v.z;
        v_s[row * 36 + q4 + 3] = v.w;
    }

    // this thread's key row -> registers
    float4 kreg[8];
    {
        int s = t >> 6, loc = t & 63;
        const float* kb = g_qkv + (size_t)((b * P2 + widx[s]) * PIX + loc) * QKVW + CC + hh * HDH;
#pragma unroll
        for (int d4 = 0; d4 < 8; d4++) kreg[d4] = *(const float4*)(kb + d4 * 4);
    }
    __syncthreads();

    // scores: thread t owns key column t
#pragma unroll 4
    for (int qi = 0; qi < PIX; qi++) {
        const float4* qrow = (const float4*)(q_s + qi * HDH);
        float acc = 0.f;
#pragma unroll
        for (int d4 = 0; d4 < 8; d4++) {
            float4 qv = qrow[d4];
            float4 kv = kreg[d4];
            acc += qv.x * kv.x + qv.y * kv.y + qv.z * kv.z + qv.w * kv.w;
        }
        sc[qi * 257 + t] = acc;
    }
    __syncthreads();

    // softmax over 256 keys per row; 4 threads per row
    {
        int part = t & 3;
        int qi = t >> 2;
        int jb = part * 64;
        float* row = sc + qi * 257;
        float mx = -1e30f;
#pragma unroll 8
        for (int j = 0; j < 64; j++) mx = fmaxf(mx, row[jb + j]);
        pmax[qi * 4 + part] = mx;
        __syncthreads();
        float rm = fmaxf(fmaxf(pmax[qi * 4], pmax[qi * 4 + 1]),
                         fmaxf(pmax[qi * 4 + 2], pmax[qi * 4 + 3]));
        float s = 0.f;
#pragma unroll 8
        for (int j = 0; j < 64; j++) {
            float e = __expf(row[jb + j] - rm);
            row[jb + j] = e;
            s += e;
        }
        psum[qi * 4 + part] = s;
        __syncthreads();
        float inv = 1.f / (psum[qi * 4] + psum[qi * 4 + 1] +
                           psum[qi * 4 + 2] + psum[qi * 4 + 3]);
#pragma unroll 8
        for (int j = 0; j < 64; j++) row[jb + j] *= inv;
    }
    __syncthreads();

    // output: thread = (d4 group, qi pair {g, g+32})
    {
        int d4 = (t & 7) * 4;
        int g = t >> 3;  // 0..31
        float4 a0 = {0, 0, 0, 0}, a1 = {0, 0, 0, 0};
        const float* s0 = sc + g * 257;
        const float* s1 = sc + (g + 32) * 257;
#pragma unroll 4
        for (int kj = 0; kj < 256; kj++) {
            float4 vv = *(const float4*)(v_s + kj * 36 + d4);
            float p0 = s0[kj], p1 = s1[kj];
            a0.x += p0 * vv.x; a0.y += p0 * vv.y; a0.z += p0 * vv.z; a0.w += p0 * vv.w;
            a1.x += p1 * vv.x; a1.y += p1 * vv.y; a1.z += p1 * vv.z; a1.w += p1 * vv.w;
        }
        *(float4*)(g_aout + (size_t)(bp * PIX + g) * CC + hh * HDH + d4) = a0;
        *(float4*)(g_aout + (size_t)(bp * PIX + g + 32) * CC + hh * HDH + d4) = a1;
    }
}

// ---------------------------------------------------------------------------
// Kernel 6: out = (attn_out + lepe) @ Wo + bo, written in image layout
// ---------------------------------------------------------------------------
__global__ __launch_bounds__(256) void gemm_out_kernel(
    const float* __restrict__ Wo, const float* __restrict__ bo,
    float* __restrict__ out)
{
    __shared__ float as[8][128];
    __shared__ float bs[8][128];
    int t = threadIdx.x;
    int tx = t & 15, ty = t >> 4;
    int m0 = blockIdx.x * 128;
    int n0 = blockIdx.y * 128;

    int arow = t >> 1;
    int aq   = (t & 1) * 4;
    int m = m0 + arow;
    int b = m / 3136, r2 = m % 3136;
    int p = r2 >> 6, pix = r2 & 63;
    int y  = (p / NW) * WS + (pix >> 3);
    int xx = (p % NW) * WS + (pix & 7);
    const float* lp = g_lepe + (size_t)(b * 3136 + y * WDIM + xx) * CC;
    const float* ap = g_aout + (size_t)m * CC;

    int brow = t >> 5;
    int bq   = (t & 31) * 4;

    float acc[8][8];
#pragma unroll
    for (int i = 0; i < 8; i++)
#pragma unroll
        for (int j = 0; j < 8; j++) acc[i][j] = 0.f;

    for (int k0 = 0; k0 < CC; k0 += 8) {
        float4 a1 = *(const float4*)(ap + k0 + aq);
        float4 a2 = *(const float4*)(lp + k0 + aq);
        as[aq + 0][arow] = a1.x + a2.x;
        as[aq + 1][arow] = a1.y + a2.y;
        as[aq + 2][arow] = a1.z + a2.z;
        as[aq + 3][arow] = a1.w + a2.w;
        *(float4*)&bs[brow][bq] = *(const float4*)(Wo + (size_t)(k0 + brow) * CC + n0 + bq);
        __syncthreads();
#pragma unroll
        for (int kk = 0; kk < 8; kk++) {
            float4 a0 = *(float4*)&as[kk][ty * 8];
            float4 a1v = *(float4*)&as[kk][ty * 8 + 4];
            float4 b0 = *(float4*)&bs[kk][tx * 8];
            float4 b1 = *(float4*)&bs[kk][tx * 8 + 4];
            float ra[8] = {a0.x, a0.y, a0.z, a0.w, a1v.x, a1v.y, a1v.z, a1v.w};
            float rb[8] = {b0.x, b0.y, b0.z, b0.w, b1.x, b1.y, b1.z, b1.w};
#pragma unroll
            for (int i = 0; i < 8; i++)
#pragma unroll
                for (int j = 0; j < 8; j++) acc[i][j] += ra[i] * rb[j];
        }
        __syncthreads();
    }
#pragma unroll
    for (int i = 0; i < 8; i++) {
        int mm = m0 + ty * 8 + i;
        int bbx = mm / 3136, rr = mm % 3136;
        int pp = rr >> 6, px = rr & 63;
        int yy = (pp / NW) * WS + (px >> 3);
        int xq = (pp % NW) * WS + (px & 7);
        float* orow = out + (size_t)(bbx * 3136 + yy * WDIM + xq) * CC + n0 + tx * 8;
#pragma unroll
        for (int j = 0; j < 8; j++) orow[j] = acc[i][j] + bo[n0 + tx * 8 + j];
    }
}

// ---------------------------------------------------------------------------
extern "C" void kernel_launch(void* const* d_in, const int* in_sizes, int n_in,
                              void* d_out, int out_size)
{
    const float* x      = (const float*)d_in[0];
    const float* Wqkv   = (const float*)d_in[1];
    const float* bqkv   = (const float*)d_in[2];
    const float* Wo     = (const float*)d_in[3];
    const float* bo     = (const float*)d_in[4];
    const float* lepe_w = (const float*)d_in[5];
    const float* lepe_b = (const float*)d_in[6];
    float* out = (float*)d_out;

    cudaFuncSetAttribute(attn_kernel,
                         cudaFuncAttributeMaxDynamicSharedMemorySize,
                         SM_FLOATS * 4);

    gemm_qkv_kernel<<<dim3(MTOT / 128, QKVW / 128), 256>>>(x, Wqkv, bqkv);
    win_mean_kernel<<<BB * P2, 256>>>();
    routing_kernel<<<BB * P2, 64>>>();
    lepe_kernel<<<(BB * HDIM * WDIM * CC) / 256, 256>>>(lepe_w, lepe_b);
    attn_kernel<<<BB * P2 * NHEAD, 256, SM_FLOATS * 4>>>();
    gemm_out_kernel<<<dim3(MTOT / 128, CC / 128), 256>>>(Wo, bo, out);
}

// round 7
// speedup vs baseline: 1.2387x; 1.2387x over previous
#include <cuda_runtime.h>
#include <cuda_bf16.h>

// Problem constants
#define BB    4
#define HDIM  56
#define WDIM  56
#define CC    256
#define NW    7
#define WS    8
#define P2    49
#define PIX   64
#define NHEAD 8
#define HDH   32
#define TOPK  4
#define MTOT  (BB * P2 * PIX)      // 12544 == BB*HDIM*WDIM
#define QKVW  768
#define SCALE 0.0625f              // 256^-0.5

// Scratch (window-ordered where noted)
__device__ float g_qkv[(size_t)MTOT * QKVW];       // (b,p,pix, 768): q|k|v
__device__ float g_qwin[BB * P2 * CC];
__device__ float g_kwin[BB * P2 * CC];
__device__ int   g_ridx[BB * P2 * TOPK];
__device__ float g_lepe[(size_t)BB * HDIM * WDIM * CC];   // image layout
__device__ float g_aout[(size_t)MTOT * CC];               // window layout

// ---------------------------------------------------------------------------
// Kernel 1: QKV GEMM  (M=12544 window-ordered rows, K=256, N=768)
// 128x128 tile, BK=16, double-buffered smem, register prefetch.
// ---------------------------------------------------------------------------
__global__ __launch_bounds__(256) void gemm_qkv_kernel(
    const float* __restrict__ x, const float* __restrict__ Wqkv,
    const float* __restrict__ bqkv)
{
    __shared__ float as[2][16][128];
    __shared__ float bs[2][16][128];
    int t = threadIdx.x;
    int tx = t & 15, ty = t >> 4;
    int m0 = blockIdx.x * 128;
    int n0 = blockIdx.y * 128;

    // A-load: thread owns row arow, k-offsets kq and kq+8 (float4 each)
    int arow = t >> 1;
    int aq   = (t & 1) * 4;
    {
        int m = m0 + arow;
        int b = m / 3136, r2 = m % 3136;
        int p = r2 >> 6, pix = r2 & 63;
        int y  = (p / NW) * WS + (pix >> 3);
        int xx = (p % NW) * WS + (pix & 7);
        // repoint: aptr fixed for the whole loop
        x += (size_t)(b * 3136 + y * WDIM + xx) * CC;
    }
    // B-load: thread owns row brow, cols bq..bq+7 (two float4)
    int brow = t >> 4;
    int bq   = (t & 15) * 8;
    const float* bptr = Wqkv + (size_t)brow * QKVW + n0 + bq;

    float acc[8][8];
#pragma unroll
    for (int i = 0; i < 8; i++)
#pragma unroll
        for (int j = 0; j < 8; j++) acc[i][j] = 0.f;

    // prime buffer 0
    {
        float4 a0 = *(const float4*)(x + aq);
        float4 a1 = *(const float4*)(x + aq + 8);
        float4 b0 = *(const float4*)(bptr);
        float4 b1 = *(const float4*)(bptr + 4);
        as[0][aq + 0][arow] = a0.x; as[0][aq + 1][arow] = a0.y;
        as[0][aq + 2][arow] = a0.z; as[0][aq + 3][arow] = a0.w;
        as[0][aq + 8][arow] = a1.x; as[0][aq + 9][arow] = a1.y;
        as[0][aq +10][arow] = a1.z; as[0][aq +11][arow] = a1.w;
        *(float4*)&bs[0][brow][bq]     = b0;
        *(float4*)&bs[0][brow][bq + 4] = b1;
    }
    __syncthreads();

    int cur = 0;
    for (int k0 = 0; k0 < CC; k0 += 16) {
        float4 pa0, pa1, pb0, pb1;
        bool more = (k0 + 16 < CC);
        if (more) {
            pa0 = *(const float4*)(x + k0 + 16 + aq);
            pa1 = *(const float4*)(x + k0 + 16 + aq + 8);
            pb0 = *(const float4*)(bptr + (size_t)(k0 + 16) * QKVW);
            pb1 = *(const float4*)(bptr + (size_t)(k0 + 16) * QKVW + 4);
        }
#pragma unroll
        for (int kk = 0; kk < 16; kk++) {
            float4 a0 = *(float4*)&as[cur][kk][ty * 8];
            float4 a1 = *(float4*)&as[cur][kk][ty * 8 + 4];
            float4 b0 = *(float4*)&bs[cur][kk][tx * 8];
            float4 b1 = *(float4*)&bs[cur][kk][tx * 8 + 4];
            float ra[8] = {a0.x, a0.y, a0.z, a0.w, a1.x, a1.y, a1.z, a1.w};
            float rb[8] = {b0.x, b0.y, b0.z, b0.w, b1.x, b1.y, b1.z, b1.w};
#pragma unroll
            for (int i = 0; i < 8; i++)
#pragma unroll
                for (int j = 0; j < 8; j++) acc[i][j] += ra[i] * rb[j];
        }
        if (more) {
            int nxt = cur ^ 1;
            as[nxt][aq + 0][arow] = pa0.x; as[nxt][aq + 1][arow] = pa0.y;
            as[nxt][aq + 2][arow] = pa0.z; as[nxt][aq + 3][arow] = pa0.w;
            as[nxt][aq + 8][arow] = pa1.x; as[nxt][aq + 9][arow] = pa1.y;
            as[nxt][aq +10][arow] = pa1.z; as[nxt][aq +11][arow] = pa1.w;
            *(float4*)&bs[nxt][brow][bq]     = pb0;
            *(float4*)&bs[nxt][brow][bq + 4] = pb1;
            __syncthreads();
            cur = nxt;
        }
    }

    float bb[8];
#pragma unroll
    for (int j = 0; j < 8; j++) bb[j] = bqkv[n0 + tx * 8 + j];
#pragma unroll
    for (int i = 0; i < 8; i++) {
        int mm = m0 + ty * 8 + i;
        float* orow = g_qkv + (size_t)mm * QKVW + n0 + tx * 8;
        float4 o0 = {acc[i][0] + bb[0], acc[i][1] + bb[1],
                     acc[i][2] + bb[2], acc[i][3] + bb[3]};
        float4 o1 = {acc[i][4] + bb[4], acc[i][5] + bb[5],
                     acc[i][6] + bb[6], acc[i][7] + bb[7]};
        *(float4*)orow = o0;
        *(float4*)(orow + 4) = o1;
    }
}

// ---------------------------------------------------------------------------
// Kernel 2: per-window means of q and k
// ---------------------------------------------------------------------------
__global__ void win_mean_kernel()
{
    int bp = blockIdx.x;            // 0..195
    int c = threadIdx.x;            // 0..255
    const float* base = g_qkv + (size_t)bp * PIX * QKVW;
    float sq = 0.f, sk = 0.f;
#pragma unroll 4
    for (int px = 0; px < PIX; px++) {
        sq += base[px * QKVW + c];
        sk += base[px * QKVW + CC + c];
    }
    g_qwin[bp * CC + c] = sq * (1.f / 64.f);
    g_kwin[bp * CC + c] = sk * (1.f / 64.f);
}

// ---------------------------------------------------------------------------
// Kernel 3: routing logits + top-4, warp-cooperative coalesced dots
// ---------------------------------------------------------------------------
__global__ __launch_bounds__(256) void routing_kernel()
{
    __shared__ float lg[P2];
    __shared__ float qsh[CC];
    int b = blockIdx.x / P2;
    int p = blockIdx.x % P2;
    int t = threadIdx.x;
    qsh[t] = g_qwin[(size_t)(b * P2 + p) * CC + t];
    __syncthreads();
    int w = t >> 5, lane = t & 31;
    for (int j = w; j < P2; j += 8) {
        const float* kr = g_kwin + (size_t)(b * P2 + j) * CC;
        float s = 0.f;
#pragma unroll
        for (int cb = 0; cb < CC; cb += 32) s += qsh[cb + lane] * kr[cb + lane];
#pragma unroll
        for (int o = 16; o; o >>= 1) s += __shfl_xor_sync(0xffffffffu, s, o);
        if (lane == 0) lg[j] = s;
    }
    __syncthreads();
    if (t == 0) {
        for (int s = 0; s < TOPK; s++) {
            float best = -1e30f; int bi = 0;
            for (int j = 0; j < P2; j++)
                if (lg[j] > best) { best = lg[j]; bi = j; }
            g_ridx[(b * P2 + p) * TOPK + s] = bi;
            lg[bi] = -1e30f;
        }
    }
}

// ---------------------------------------------------------------------------
// Kernel 4: lepe = depthwise 5x5 conv over v.
// One block per (b, window, 64-channel chunk); 12x12x64 halo in smem,
// 25 weights in registers. Index math only on halo load.
// ---------------------------------------------------------------------------
__global__ __launch_bounds__(256) void lepe_kernel(
    const float* __restrict__ lw, const float* __restrict__ lb)
{
    __shared__ float halo[144 * 64];   // 36864 B
    int blk = blockIdx.x;              // ((b*49+p)*4 + cq)
    int cq = blk & 3;
    int bp = blk >> 2;
    int b = bp / P2, p = bp % P2;
    int y0 = (p / NW) * WS - 2;
    int x0 = (p % NW) * WS - 2;
    int t = threadIdx.x;

    // load halo: 2304 float4 total, 9 per thread
#pragma unroll
    for (int i = 0; i < 9; i++) {
        int f = t + i * 256;
        int pix = f >> 4;              // 0..143
        int q4 = (f & 15) * 4;
        int hy = pix / 12, hx = pix % 12;
        int yy = y0 + hy, xs = x0 + hx;
        float4 v = {0.f, 0.f, 0.f, 0.f};
        if (yy >= 0 && yy < HDIM && xs >= 0 && xs < WDIM) {
            int sp = (yy >> 3) * NW + (xs >> 3);
            int spx = ((yy & 7) << 3) + (xs & 7);
            v = *(const float4*)(g_qkv +
                (size_t)((b * P2 + sp) * PIX + spx) * QKVW + 2 * CC + cq * 64 + q4);
        }
        *(float4*)&halo[pix * 64 + q4] = v;
    }

    int c = t & 63;
    int gc = cq * 64 + c;
    float wr[25];
#pragma unroll
    for (int k = 0; k < 25; k++) wr[k] = lw[k * CC + gc];
    float bias = lb[gc];
    __syncthreads();

    int tp = t >> 6;   // 0..3 : 16 pixels each
#pragma unroll
    for (int u = 0; u < 16; u++) {
        int p8 = tp * 16 + u;
        int ly = p8 >> 3, lx = p8 & 7;
        float acc = bias;
#pragma unroll
        for (int dy = 0; dy < 5; dy++)
#pragma unroll
            for (int dx = 0; dx < 5; dx++)
                acc += halo[((ly + dy) * 12 + (lx + dx)) * 64 + c] * wr[dy * 5 + dx];
        g_lepe[((size_t)b * 3136 + (y0 + 2 + ly) * WDIM + (x0 + 2 + lx)) * CC + gc] = acc;
    }
}

// ---------------------------------------------------------------------------
// Kernel 5: attention per (b, window, head).  (unchanged from R4)
// ---------------------------------------------------------------------------
#define SM_Q   0
#define SM_V   2048
#define SM_SC  (2048 + 256 * 36)                 // 11264
#define SM_PM  (SM_SC + 64 * 257)                // 27712
#define SM_PS  (SM_PM + 256)                     // 27968
#define SM_FLOATS (SM_PS + 256)                  // 28224 -> 112896 B

__global__ __launch_bounds__(256) void attn_kernel()
{
    extern __shared__ float sm[];
    float* q_s  = sm + SM_Q;
    float* v_s  = sm + SM_V;
    float* sc   = sm + SM_SC;
    float* pmax = sm + SM_PM;
    float* psum = sm + SM_PS;

    int blk = blockIdx.x;
    int b  = blk / (P2 * NHEAD);
    int p  = (blk / NHEAD) % P2;
    int hh = blk % NHEAD;
    int bp = b * P2 + p;
    int t = threadIdx.x;

    int widx[TOPK];
#pragma unroll
    for (int s = 0; s < TOPK; s++) widx[s] = g_ridx[bp * TOPK + s];

#pragma unroll
    for (int i = 0; i < 2; i++) {
        int f = t + i * 256;
        int px = f >> 3, q4 = (f & 7) * 4;
        float4 v = *(const float4*)(g_qkv + (size_t)(bp * PIX + px) * QKVW + hh * HDH + q4);
        float4 o; o.x = v.x * SCALE; o.y = v.y * SCALE; o.z = v.z * SCALE; o.w = v.w * SCALE;
        *(float4*)&q_s[px * HDH + q4] = o;
    }

#pragma unroll
    for (int i = 0; i < 8; i++) {
        int f = t + i * 256;
        int row = f >> 3, q4 = (f & 7) * 4;
        int s = row >> 6, loc = row & 63;
        float4 v = *(const float4*)(g_qkv +
            (size_t)((b * P2 + widx[s]) * PIX + loc) * QKVW + 2 * CC + hh * HDH + q4);
        v_s[row * 36 + q4 + 0] = v.x;
        v_s[row * 36 + q4 + 1] = v.y;
        v_s[row * 36 + q4 + 2] = v.z;
        v_s[row * 36 + q4 + 3] = v.w;
    }

    float4 kreg[8];
    {
        int s = t >> 6, loc = t & 63;
        const float* kb = g_qkv + (size_t)((b * P2 + widx[s]) * PIX + loc) * QKVW + CC + hh * HDH;
#pragma unroll
        for (int d4 = 0; d4 < 8; d4++) kreg[d4] = *(const float4*)(kb + d4 * 4);
    }
    __syncthreads();

#pragma unroll 4
    for (int qi = 0; qi < PIX; qi++) {
        const float4* qrow = (const float4*)(q_s + qi * HDH);
        float acc = 0.f;
#pragma unroll
        for (int d4 = 0; d4 < 8; d4++) {
            float4 qv = qrow[d4];
            float4 kv = kreg[d4];
            acc += qv.x * kv.x + qv.y * kv.y + qv.z * kv.z + qv.w * kv.w;
        }
        sc[qi * 257 + t] = acc;
    }
    __syncthreads();

    {
        int part = t & 3;
        int qi = t >> 2;
        int jb = part * 64;
        float* row = sc + qi * 257;
        float mx = -1e30f;
#pragma unroll 8
        for (int j = 0; j < 64; j++) mx = fmaxf(mx, row[jb + j]);
        pmax[qi * 4 + part] = mx;
        __syncthreads();
        float rm = fmaxf(fmaxf(pmax[qi * 4], pmax[qi * 4 + 1]),
                         fmaxf(pmax[qi * 4 + 2], pmax[qi * 4 + 3]));
        float s = 0.f;
#pragma unroll 8
        for (int j = 0; j < 64; j++) {
            float e = __expf(row[jb + j] - rm);
            row[jb + j] = e;
            s += e;
        }
        psum[qi * 4 + part] = s;
        __syncthreads();
        float inv = 1.f / (psum[qi * 4] + psum[qi * 4 + 1] +
                           psum[qi * 4 + 2] + psum[qi * 4 + 3]);
#pragma unroll 8
        for (int j = 0; j < 64; j++) row[jb + j] *= inv;
    }
    __syncthreads();

    {
        int d4 = (t & 7) * 4;
        int g = t >> 3;
        float4 a0 = {0, 0, 0, 0}, a1 = {0, 0, 0, 0};
        const float* s0 = sc + g * 257;
        const float* s1 = sc + (g + 32) * 257;
#pragma unroll 4
        for (int kj = 0; kj < 256; kj++) {
            float4 vv = *(const float4*)(v_s + kj * 36 + d4);
            float p0 = s0[kj], p1 = s1[kj];
            a0.x += p0 * vv.x; a0.y += p0 * vv.y; a0.z += p0 * vv.z; a0.w += p0 * vv.w;
            a1.x += p1 * vv.x; a1.y += p1 * vv.y; a1.z += p1 * vv.z; a1.w += p1 * vv.w;
        }
        *(float4*)(g_aout + (size_t)(bp * PIX + g) * CC + hh * HDH + d4) = a0;
        *(float4*)(g_aout + (size_t)(bp * PIX + g + 32) * CC + hh * HDH + d4) = a1;
    }
}

// ---------------------------------------------------------------------------
// Kernel 6: out = (attn_out + lepe) @ Wo + bo, image layout.
// Same double-buffered scheme as kernel 1.
// ---------------------------------------------------------------------------
__global__ __launch_bounds__(256) void gemm_out_kernel(
    const float* __restrict__ Wo, const float* __restrict__ bo,
    float* __restrict__ out)
{
    __shared__ float as[2][16][128];
    __shared__ float bs[2][16][128];
    int t = threadIdx.x;
    int tx = t & 15, ty = t >> 4;
    int m0 = blockIdx.x * 128;
    int n0 = blockIdx.y * 128;

    int arow = t >> 1;
    int aq   = (t & 1) * 4;
    const float* lp;
    const float* ap;
    {
        int m = m0 + arow;
        int b = m / 3136, r2 = m % 3136;
        int p = r2 >> 6, pix = r2 & 63;
        int y  = (p / NW) * WS + (pix >> 3);
        int xx = (p % NW) * WS + (pix & 7);
        lp = g_lepe + (size_t)(b * 3136 + y * WDIM + xx) * CC;
        ap = g_aout + (size_t)m * CC;
    }
    int brow = t >> 4;
    int bq   = (t & 15) * 8;
    const float* bptr = Wo + (size_t)brow * CC + n0 + bq;

    float acc[8][8];
#pragma unroll
    for (int i = 0; i < 8; i++)
#pragma unroll
        for (int j = 0; j < 8; j++) acc[i][j] = 0.f;

    {
        float4 a0 = *(const float4*)(ap + aq);
        float4 a1 = *(const float4*)(ap + aq + 8);
        float4 l0 = *(const float4*)(lp + aq);
        float4 l1 = *(const float4*)(lp + aq + 8);
        float4 b0 = *(const float4*)(bptr);
        float4 b1 = *(const float4*)(bptr + 4);
        as[0][aq + 0][arow] = a0.x + l0.x; as[0][aq + 1][arow] = a0.y + l0.y;
        as[0][aq + 2][arow] = a0.z + l0.z; as[0][aq + 3][arow] = a0.w + l0.w;
        as[0][aq + 8][arow] = a1.x + l1.x; as[0][aq + 9][arow] = a1.y + l1.y;
        as[0][aq +10][arow] = a1.z + l1.z; as[0][aq +11][arow] = a1.w + l1.w;
        *(float4*)&bs[0][brow][bq]     = b0;
        *(float4*)&bs[0][brow][bq + 4] = b1;
    }
    __syncthreads();

    int cur = 0;
    for (int k0 = 0; k0 < CC; k0 += 16) {
        float4 pa0, pa1, pl0, pl1, pb0, pb1;
        bool more = (k0 + 16 < CC);
        if (more) {
            pa0 = *(const float4*)(ap + k0 + 16 + aq);
            pa1 = *(const float4*)(ap + k0 + 16 + aq + 8);
            pl0 = *(const float4*)(lp + k0 + 16 + aq);
            pl1 = *(const float4*)(lp + k0 + 16 + aq + 8);
            pb0 = *(const float4*)(bptr + (size_t)(k0 + 16) * CC);
            pb1 = *(const float4*)(bptr + (size_t)(k0 + 16) * CC + 4);
        }
#pragma unroll
        for (int kk = 0; kk < 16; kk++) {
            float4 a0 = *(float4*)&as[cur][kk][ty * 8];
            float4 a1 = *(float4*)&as[cur][kk][ty * 8 + 4];
            float4 b0 = *(float4*)&bs[cur][kk][tx * 8];
            float4 b1 = *(float4*)&bs[cur][kk][tx * 8 + 4];
            float ra[8] = {a0.x, a0.y, a0.z, a0.w, a1.x, a1.y, a1.z, a1.w};
            float rb[8] = {b0.x, b0.y, b0.z, b0.w, b1.x, b1.y, b1.z, b1.w};
#pragma unroll
            for (int i = 0; i < 8; i++)
#pragma unroll
                for (int j = 0; j < 8; j++) acc[i][j] += ra[i] * rb[j];
        }
        if (more) {
            int nxt = cur ^ 1;
            as[nxt][aq + 0][arow] = pa0.x + pl0.x; as[nxt][aq + 1][arow] = pa0.y + pl0.y;
            as[nxt][aq + 2][arow] = pa0.z + pl0.z; as[nxt][aq + 3][arow] = pa0.w + pl0.w;
            as[nxt][aq + 8][arow] = pa1.x + pl1.x; as[nxt][aq + 9][arow] = pa1.y + pl1.y;
            as[nxt][aq +10][arow] = pa1.z + pl1.z; as[nxt][aq +11][arow] = pa1.w + pl1.w;
            *(float4*)&bs[nxt][brow][bq]     = pb0;
            *(float4*)&bs[nxt][brow][bq + 4] = pb1;
            __syncthreads();
            cur = nxt;
        }
    }

    float bbr[8];
#pragma unroll
    for (int j = 0; j < 8; j++) bbr[j] = bo[n0 + tx * 8 + j];
#pragma unroll
    for (int i = 0; i < 8; i++) {
        int mm = m0 + ty * 8 + i;
        int bbx = mm / 3136, rr = mm % 3136;
        int pp = rr >> 6, px = rr & 63;
        int yy = (pp / NW) * WS + (px >> 3);
        int xq = (pp % NW) * WS + (px & 7);
        float* orow = out + (size_t)(bbx * 3136 + yy * WDIM + xq) * CC + n0 + tx * 8;
        float4 o0 = {acc[i][0] + bbr[0], acc[i][1] + bbr[1],
                     acc[i][2] + bbr[2], acc[i][3] + bbr[3]};
        float4 o1 = {acc[i][4] + bbr[4], acc[i][5] + bbr[5],
                     acc[i][6] + bbr[6], acc[i][7] + bbr[7]};
        *(float4*)orow = o0;
        *(float4*)(orow + 4) = o1;
    }
}

// ---------------------------------------------------------------------------
extern "C" void kernel_launch(void* const* d_in, const int* in_sizes, int n_in,
                              void* d_out, int out_size)
{
    const float* x      = (const float*)d_in[0];
    const float* Wqkv   = (const float*)d_in[1];
    const float* bqkv   = (const float*)d_in[2];
    const float* Wo     = (const float*)d_in[3];
    const float* bo     = (const float*)d_in[4];
    const float* lepe_w = (const float*)d_in[5];
    const float* lepe_b = (const float*)d_in[6];
    float* out = (float*)d_out;

    cudaFuncSetAttribute(attn_kernel,
                         cudaFuncAttributeMaxDynamicSharedMemorySize,
                         SM_FLOATS * 4);

    gemm_qkv_kernel<<<dim3(MTOT / 128, QKVW / 128), 256>>>(x, Wqkv, bqkv);
    win_mean_kernel<<<BB * P2, 256>>>();
    routing_kernel<<<BB * P2, 256>>>();
    lepe_kernel<<<BB * P2 * 4, 256>>>(lepe_w, lepe_b);
    attn_kernel<<<BB * P2 * NHEAD, 256, SM_FLOATS * 4>>>();
    gemm_out_kernel<<<dim3(MTOT / 128, CC / 128), 256>>>(Wo, bo, out);
}

// round 10
// speedup vs baseline: 1.5188x; 1.2261x over previous
#include <cuda_runtime.h>
#include <cuda_bf16.h>
#include <cstdint>

// Problem constants
#define BB    4
#define HDIM  56
#define WDIM  56
#define CC    256
#define NW    7
#define WS    8
#define P2    49
#define PIX   64
#define NHEAD 8
#define HDH   32
#define TOPK  4
#define MTOT  (BB * P2 * PIX)      // 12544 == BB*HDIM*WDIM
#define QKVW  768
#define SCALE 0.0625f              // 256^-0.5

// Scratch (window-ordered where noted)
__device__ float g_qkv[(size_t)MTOT * QKVW];       // (b,p,pix, 768): q|k|v
__device__ float g_qwin[BB * P2 * CC];
__device__ float g_kwin[BB * P2 * CC];
__device__ int   g_ridx[BB * P2 * TOPK];
__device__ float g_lepe[(size_t)BB * HDIM * WDIM * CC];   // image layout
__device__ float g_aout[(size_t)MTOT * CC];               // window layout

// ---------------------------------------------------------------------------
// tf32 helpers
// ---------------------------------------------------------------------------
__device__ __forceinline__ uint32_t f2tf(float f) {
    uint32_t u;
    asm("cvt.rna.tf32.f32 %0, %1;" : "=r"(u) : "f"(f));
    return u;
}

__device__ __forceinline__ void mma_tf32(float4& d, const uint32_t a[4],
                                         const uint32_t b[2]) {
    asm volatile(
        "mma.sync.aligned.m16n8k8.row.col.f32.tf32.tf32.f32 "
        "{%0,%1,%2,%3},{%4,%5,%6,%7},{%8,%9},{%0,%1,%2,%3};"
        : "+f"(d.x), "+f"(d.y), "+f"(d.z), "+f"(d.w)
        : "r"(a[0]), "r"(a[1]), "r"(a[2]), "r"(a[3]), "r"(b[0]), "r"(b[1]));
}

#define BK    16
#define ASTR  136

// ---------------------------------------------------------------------------
// Kernel 1: QKV GEMM via tf32 tensor cores.
// 128x128 block, 8 warps (2x4), warp tile 64x32, m16n8k8 tiles.
// ---------------------------------------------------------------------------
__global__ __launch_bounds__(256) void gemm_qkv_tc(
    const float* __restrict__ x, const float* __restrict__ Wqkv,
    const float* __restrict__ bqkv)
{
    __shared__ uint32_t as[2][BK][ASTR];   // [k][m]
    __shared__ uint32_t bs[2][BK][ASTR];   // [k][n]
    int t = threadIdx.x;
    int warp = t >> 5, lane = t & 31;
    int wm = warp >> 2, wn = warp & 3;
    int m0 = blockIdx.x * 128;
    int n0 = blockIdx.y * 128;

    // A loader: thread owns row (t&127), k-half (t>>7)*8 (two float4)
    int arow = t & 127;
    int ka   = (t >> 7) * 8;
    {
        int m = m0 + arow;
        int b = m / 3136, r2 = m % 3136;
        int p = r2 >> 6, pix = r2 & 63;
        int y  = (p / NW) * WS + (pix >> 3);
        int xx = (p % NW) * WS + (pix & 7);
        x += (size_t)(b * 3136 + y * WDIM + xx) * CC;
    }
    // B loader: thread owns row t>>4, cols (t&15)*8 (two float4)
    int brow = t >> 4;
    int bq   = (t & 15) * 8;

    float4 acc[4][4];
#pragma unroll
    for (int i = 0; i < 4; i++)
#pragma unroll
        for (int j = 0; j < 4; j++) acc[i][j] = make_float4(0.f, 0.f, 0.f, 0.f);

    // prime buffer 0
    {
        float4 a0 = *(const float4*)(x + ka);
        float4 a1 = *(const float4*)(x + ka + 4);
        float4 b0 = *(const float4*)(Wqkv + (size_t)brow * QKVW + n0 + bq);
        float4 b1 = *(const float4*)(Wqkv + (size_t)brow * QKVW + n0 + bq + 4);
        as[0][ka + 0][arow] = f2tf(a0.x); as[0][ka + 1][arow] = f2tf(a0.y);
        as[0][ka + 2][arow] = f2tf(a0.z); as[0][ka + 3][arow] = f2tf(a0.w);
        as[0][ka + 4][arow] = f2tf(a1.x); as[0][ka + 5][arow] = f2tf(a1.y);
        as[0][ka + 6][arow] = f2tf(a1.z); as[0][ka + 7][arow] = f2tf(a1.w);
        uint4 u0 = {f2tf(b0.x), f2tf(b0.y), f2tf(b0.z), f2tf(b0.w)};
        uint4 u1 = {f2tf(b1.x), f2tf(b1.y), f2tf(b1.z), f2tf(b1.w)};
        *(uint4*)&bs[0][brow][bq]     = u0;
        *(uint4*)&bs[0][brow][bq + 4] = u1;
    }
    __syncthreads();

    int r = lane >> 2, c = lane & 3;
    int cur = 0;
    for (int k0 = 0; k0 < CC; k0 += BK) {
        bool more = (k0 + BK < CC);
        float4 pa0, pa1, pb0, pb1;
        if (more) {
            pa0 = *(const float4*)(x + k0 + BK + ka);
            pa1 = *(const float4*)(x + k0 + BK + ka + 4);
            pb0 = *(const float4*)(Wqkv + (size_t)(k0 + BK + brow) * QKVW + n0 + bq);
            pb1 = *(const float4*)(Wqkv + (size_t)(k0 + BK + brow) * QKVW + n0 + bq + 4);
        }
#pragma unroll
        for (int kc = 0; kc < 2; kc++) {
            int kb = kc * 8;
            uint32_t bf[4][2];
#pragma unroll
            for (int nt = 0; nt < 4; nt++) {
                int n = wn * 32 + nt * 8 + r;
                bf[nt][0] = bs[cur][kb + c][n];
                bf[nt][1] = bs[cur][kb + 4 + c][n];
            }
#pragma unroll
            for (int mt = 0; mt < 4; mt++) {
                int m = wm * 64 + mt * 16;
                uint32_t af[4];
                af[0] = as[cur][kb + c][m + r];
                af[1] = as[cur][kb + c][m + r + 8];
                af[2] = as[cur][kb + 4 + c][m + r];
                af[3] = as[cur][kb + 4 + c][m + r + 8];
#pragma unroll
                for (int nt = 0; nt < 4; nt++) mma_tf32(acc[mt][nt], af, bf[nt]);
            }
        }
        if (more) {
            int nxt = cur ^ 1;
            as[nxt][ka + 0][arow] = f2tf(pa0.x); as[nxt][ka + 1][arow] = f2tf(pa0.y);
            as[nxt][ka + 2][arow] = f2tf(pa0.z); as[nxt][ka + 3][arow] = f2tf(pa0.w);
            as[nxt][ka + 4][arow] = f2tf(pa1.x); as[nxt][ka + 5][arow] = f2tf(pa1.y);
            as[nxt][ka + 6][arow] = f2tf(pa1.z); as[nxt][ka + 7][arow] = f2tf(pa1.w);
            uint4 u0 = {f2tf(pb0.x), f2tf(pb0.y), f2tf(pb0.z), f2tf(pb0.w)};
            uint4 u1 = {f2tf(pb1.x), f2tf(pb1.y), f2tf(pb1.z), f2tf(pb1.w)};
            *(uint4*)&bs[nxt][brow][bq]     = u0;
            *(uint4*)&bs[nxt][brow][bq + 4] = u1;
            __syncthreads();
            cur = nxt;
        }
    }

    // epilogue: d0,d1 -> (r, 2c..2c+1); d2,d3 -> (r+8, 2c..2c+1)
    int c2 = c * 2;
#pragma unroll
    for (int nt = 0; nt < 4; nt++) {
        int col = n0 + wn * 32 + nt * 8 + c2;
        float2 bb = *(const float2*)&bqkv[col];
#pragma unroll
        for (int mt = 0; mt < 4; mt++) {
            int mm = m0 + wm * 64 + mt * 16 + r;
            float4 a = acc[mt][nt];
            float2 o0 = {a.x + bb.x, a.y + bb.y};
            float2 o1 = {a.z + bb.x, a.w + bb.y};
            *(float2*)(g_qkv + (size_t)mm * QKVW + col) = o0;
            *(float2*)(g_qkv + (size_t)(mm + 8) * QKVW + col) = o1;
        }
    }
}

// ---------------------------------------------------------------------------
// Kernel 2: per-window means of q and k
// ---------------------------------------------------------------------------
__global__ void win_mean_kernel()
{
    int bp = blockIdx.x;            // 0..195
    int c = threadIdx.x;            // 0..255
    const float* base = g_qkv + (size_t)bp * PIX * QKVW;
    float sq = 0.f, sk = 0.f;
#pragma unroll 4
    for (int px = 0; px < PIX; px++) {
        sq += base[px * QKVW + c];
        sk += base[px * QKVW + CC + c];
    }
    g_qwin[bp * CC + c] = sq * (1.f / 64.f);
    g_kwin[bp * CC + c] = sk * (1.f / 64.f);
}

// ---------------------------------------------------------------------------
// Kernel 3: routing logits + top-4, warp-cooperative coalesced dots
// ---------------------------------------------------------------------------
__global__ __launch_bounds__(256) void routing_kernel()
{
    __shared__ float lg[P2];
    __shared__ float qsh[CC];
    int b = blockIdx.x / P2;
    int p = blockIdx.x % P2;
    int t = threadIdx.x;
    qsh[t] = g_qwin[(size_t)(b * P2 + p) * CC + t];
    __syncthreads();
    int w = t >> 5, lane = t & 31;
    for (int j = w; j < P2; j += 8) {
        const float* kr = g_kwin + (size_t)(b * P2 + j) * CC;
        float s = 0.f;
#pragma unroll
        for (int cb = 0; cb < CC; cb += 32) s += qsh[cb + lane] * kr[cb + lane];
#pragma unroll
        for (int o = 16; o; o >>= 1) s += __shfl_xor_sync(0xffffffffu, s, o);
        if (lane == 0) lg[j] = s;
    }
    __syncthreads();
    if (t == 0) {
        for (int s = 0; s < TOPK; s++) {
            float best = -1e30f; int bi = 0;
            for (int j = 0; j < P2; j++)
                if (lg[j] > best) { best = lg[j]; bi = j; }
            g_ridx[(b * P2 + p) * TOPK + s] = bi;
            lg[bi] = -1e30f;
        }
    }
}

// ---------------------------------------------------------------------------
// Kernel 4: lepe = depthwise 5x5 conv over v (halo-tile version)
// ---------------------------------------------------------------------------
__global__ __launch_bounds__(256) void lepe_kernel(
    const float* __restrict__ lw, const float* __restrict__ lb)
{
    __shared__ float halo[144 * 64];   // 36864 B
    int blk = blockIdx.x;              // ((b*49+p)*4 + cq)
    int cq = blk & 3;
    int bp = blk >> 2;
    int b = bp / P2, p = bp % P2;
    int y0 = (p / NW) * WS - 2;
    int x0 = (p % NW) * WS - 2;
    int t = threadIdx.x;

#pragma unroll
    for (int i = 0; i < 9; i++) {
        int f = t + i * 256;
        int pix = f >> 4;
        int q4 = (f & 15) * 4;
        int hy = pix / 12, hx = pix % 12;
        int yy = y0 + hy, xs = x0 + hx;
        float4 v = {0.f, 0.f, 0.f, 0.f};
        if (yy >= 0 && yy < HDIM && xs >= 0 && xs < WDIM) {
            int sp = (yy >> 3) * NW + (xs >> 3);
            int spx = ((yy & 7) << 3) + (xs & 7);
            v = *(const float4*)(g_qkv +
                (size_t)((b * P2 + sp) * PIX + spx) * QKVW + 2 * CC + cq * 64 + q4);
        }
        *(float4*)&halo[pix * 64 + q4] = v;
    }

    int c = t & 63;
    int gc = cq * 64 + c;
    float wr[25];
#pragma unroll
    for (int k = 0; k < 25; k++) wr[k] = lw[k * CC + gc];
    float bias = lb[gc];
    __syncthreads();

    int tp = t >> 6;
#pragma unroll
    for (int u = 0; u < 16; u++) {
        int p8 = tp * 16 + u;
        int ly = p8 >> 3, lx = p8 & 7;
        float acc = bias;
#pragma unroll
        for (int dy = 0; dy < 5; dy++)
#pragma unroll
            for (int dx = 0; dx < 5; dx++)
                acc += halo[((ly + dy) * 12 + (lx + dx)) * 64 + c] * wr[dy * 5 + dx];
        g_lepe[((size_t)b * 3136 + (y0 + 2 + ly) * WDIM + (x0 + 2 + lx)) * CC + gc] = acc;
    }
}

// ---------------------------------------------------------------------------
// Kernel 5: attention per (b, window, head). (unchanged)
// ---------------------------------------------------------------------------
#define SM_Q   0
#define SM_V   2048
#define SM_SC  (2048 + 256 * 36)                 // 11264
#define SM_PM  (SM_SC + 64 * 257)                // 27712
#define SM_PS  (SM_PM + 256)                     // 27968
#define SM_FLOATS (SM_PS + 256)                  // 28224 -> 112896 B

__global__ __launch_bounds__(256) void attn_kernel()
{
    extern __shared__ float sm[];
    float* q_s  = sm + SM_Q;
    float* v_s  = sm + SM_V;
    float* sc   = sm + SM_SC;
    float* pmax = sm + SM_PM;
    float* psum = sm + SM_PS;

    int blk = blockIdx.x;
    int b  = blk / (P2 * NHEAD);
    int p  = (blk / NHEAD) % P2;
    int hh = blk % NHEAD;
    int bp = b * P2 + p;
    int t = threadIdx.x;

    int widx[TOPK];
#pragma unroll
    for (int s = 0; s < TOPK; s++) widx[s] = g_ridx[bp * TOPK + s];

#pragma unroll
    for (int i = 0; i < 2; i++) {
        int f = t + i * 256;
        int px = f >> 3, q4 = (f & 7) * 4;
        float4 v = *(const float4*)(g_qkv + (size_t)(bp * PIX + px) * QKVW + hh * HDH + q4);
        float4 o; o.x = v.x * SCALE; o.y = v.y * SCALE; o.z = v.z * SCALE; o.w = v.w * SCALE;
        *(float4*)&q_s[px * HDH + q4] = o;
    }

#pragma unroll
    for (int i = 0; i < 8; i++) {
        int f = t + i * 256;
        int row = f >> 3, q4 = (f & 7) * 4;
        int s = row >> 6, loc = row & 63;
        float4 v = *(const float4*)(g_qkv +
            (size_t)((b * P2 + widx[s]) * PIX + loc) * QKVW + 2 * CC + hh * HDH + q4);
        v_s[row * 36 + q4 + 0] = v.x;
        v_s[row * 36 + q4 + 1] = v.y;
        v_s[row * 36 + q4 + 2] = v.z;
        v_s[row * 36 + q4 + 3] = v.w;
    }

    float4 kreg[8];
    {
        int s = t >> 6, loc = t & 63;
        const float* kb = g_qkv + (size_t)((b * P2 + widx[s]) * PIX + loc) * QKVW + CC + hh * HDH;
#pragma unroll
        for (int d4 = 0; d4 < 8; d4++) kreg[d4] = *(const float4*)(kb + d4 * 4);
    }
    __syncthreads();

#pragma unroll 4
    for (int qi = 0; qi < PIX; qi++) {
        const float4* qrow = (const float4*)(q_s + qi * HDH);
        float acc = 0.f;
#pragma unroll
        for (int d4 = 0; d4 < 8; d4++) {
            float4 qv = qrow[d4];
            float4 kv = kreg[d4];
            acc += qv.x * kv.x + qv.y * kv.y + qv.z * kv.z + qv.w * kv.w;
        }
        sc[qi * 257 + t] = acc;
    }
    __syncthreads();

    {
        int part = t & 3;
        int qi = t >> 2;
        int jb = part * 64;
        float* row = sc + qi * 257;
        float mx = -1e30f;
#pragma unroll 8
        for (int j = 0; j < 64; j++) mx = fmaxf(mx, row[jb + j]);
        pmax[qi * 4 + part] = mx;
        __syncthreads();
        float rm = fmaxf(fmaxf(pmax[qi * 4], pmax[qi * 4 + 1]),
                         fmaxf(pmax[qi * 4 + 2], pmax[qi * 4 + 3]));
        float s = 0.f;
#pragma unroll 8
        for (int j = 0; j < 64; j++) {
            float e = __expf(row[jb + j] - rm);
            row[jb + j] = e;
            s += e;
        }
        psum[qi * 4 + part] = s;
        __syncthreads();
        float inv = 1.f / (psum[qi * 4] + psum[qi * 4 + 1] +
                           psum[qi * 4 + 2] + psum[qi * 4 + 3]);
#pragma unroll 8
        for (int j = 0; j < 64; j++) row[jb + j] *= inv;
    }
    __syncthreads();

    {
        int d4 = (t & 7) * 4;
        int g = t >> 3;
        float4 a0 = {0, 0, 0, 0}, a1 = {0, 0, 0, 0};
        const float* s0 = sc + g * 257;
        const float* s1 = sc + (g + 32) * 257;
#pragma unroll 4
        for (int kj = 0; kj < 256; kj++) {
            float4 vv = *(const float4*)(v_s + kj * 36 + d4);
            float p0 = s0[kj], p1 = s1[kj];
            a0.x += p0 * vv.x; a0.y += p0 * vv.y; a0.z += p0 * vv.z; a0.w += p0 * vv.w;
            a1.x += p1 * vv.x; a1.y += p1 * vv.y; a1.z += p1 * vv.z; a1.w += p1 * vv.w;
        }
        *(float4*)(g_aout + (size_t)(bp * PIX + g) * CC + hh * HDH + d4) = a0;
        *(float4*)(g_aout + (size_t)(bp * PIX + g + 32) * CC + hh * HDH + d4) = a1;
    }
}

// ---------------------------------------------------------------------------
// Kernel 6: out = (attn_out + lepe) @ Wo + bo via tf32 tensor cores,
// image-layout output.
// ---------------------------------------------------------------------------
__global__ __launch_bounds__(256) void gemm_out_tc(
    const float* __restrict__ Wo, const float* __restrict__ bo,
    float* __restrict__ out)
{
    __shared__ uint32_t as[2][BK][ASTR];
    __shared__ uint32_t bs[2][BK][ASTR];
    int t = threadIdx.x;
    int warp = t >> 5, lane = t & 31;
    int wm = warp >> 2, wn = warp & 3;
    int m0 = blockIdx.x * 128;
    int n0 = blockIdx.y * 128;

    int arow = t & 127;
    int ka   = (t >> 7) * 8;
    const float* ap;
    const float* lp;
    {
        int m = m0 + arow;
        int b = m / 3136, r2 = m % 3136;
        int p = r2 >> 6, pix = r2 & 63;
        int y  = (p / NW) * WS + (pix >> 3);
        int xx = (p % NW) * WS + (pix & 7);
        lp = g_lepe + (size_t)(b * 3136 + y * WDIM + xx) * CC;
        ap = g_aout + (size_t)m * CC;
    }
    int brow = t >> 4;
    int bq   = (t & 15) * 8;

    float4 acc[4][4];
#pragma unroll
    for (int i = 0; i < 4; i++)
#pragma unroll
        for (int j = 0; j < 4; j++) acc[i][j] = make_float4(0.f, 0.f, 0.f, 0.f);

    {
        float4 a0 = *(const float4*)(ap + ka);
        float4 a1 = *(const float4*)(ap + ka + 4);
        float4 l0 = *(const float4*)(lp + ka);
        float4 l1 = *(const float4*)(lp + ka + 4);
        float4 b0 = *(const float4*)(Wo + (size_t)brow * CC + n0 + bq);
        float4 b1 = *(const float4*)(Wo + (size_t)brow * CC + n0 + bq + 4);
        as[0][ka + 0][arow] = f2tf(a0.x + l0.x); as[0][ka + 1][arow] = f2tf(a0.y + l0.y);
        as[0][ka + 2][arow] = f2tf(a0.z + l0.z); as[0][ka + 3][arow] = f2tf(a0.w + l0.w);
        as[0][ka + 4][arow] = f2tf(a1.x + l1.x); as[0][ka + 5][arow] = f2tf(a1.y + l1.y);
        as[0][ka + 6][arow] = f2tf(a1.z + l1.z); as[0][ka + 7][arow] = f2tf(a1.w + l1.w);
        uint4 u0 = {f2tf(b0.x), f2tf(b0.y), f2tf(b0.z), f2tf(b0.w)};
        uint4 u1 = {f2tf(b1.x), f2tf(b1.y), f2tf(b1.z), f2tf(b1.w)};
        *(uint4*)&bs[0][brow][bq]     = u0;
        *(uint4*)&bs[0][brow][bq + 4] = u1;
    }
    __syncthreads();

    int r = lane >> 2, c = lane & 3;
    int cur = 0;
    for (int k0 = 0; k0 < CC; k0 += BK) {
        bool more = (k0 + BK < CC);
        float4 pa0, pa1, pl0, pl1, pb0, pb1;
        if (more) {
            pa0 = *(const float4*)(ap + k0 + BK + ka);
            pa1 = *(const float4*)(ap + k0 + BK + ka + 4);
            pl0 = *(const float4*)(lp + k0 + BK + ka);
            pl1 = *(const float4*)(lp + k0 + BK + ka + 4);
            pb0 = *(const float4*)(Wo + (size_t)(k0 + BK + brow) * CC + n0 + bq);
            pb1 = *(const float4*)(Wo + (size_t)(k0 + BK + brow) * CC + n0 + bq + 4);
        }
#pragma unroll
        for (int kc = 0; kc < 2; kc++) {
            int kb = kc * 8;
            uint32_t bf[4][2];
#pragma unroll
            for (int nt = 0; nt < 4; nt++) {
                int n = wn * 32 + nt * 8 + r;
                bf[nt][0] = bs[cur][kb + c][n];
                bf[nt][1] = bs[cur][kb + 4 + c][n];
            }
#pragma unroll
            for (int mt = 0; mt < 4; mt++) {
                int m = wm * 64 + mt * 16;
                uint32_t af[4];
                af[0] = as[cur][kb + c][m + r];
                af[1] = as[cur][kb + c][m + r + 8];
                af[2] = as[cur][kb + 4 + c][m + r];
                af[3] = as[cur][kb + 4 + c][m + r + 8];
#pragma unroll
                for (int nt = 0; nt < 4; nt++) mma_tf32(acc[mt][nt], af, bf[nt]);
            }
        }
        if (more) {
            int nxt = cur ^ 1;
            as[nxt][ka + 0][arow] = f2tf(pa0.x + pl0.x); as[nxt][ka + 1][arow] = f2tf(pa0.y + pl0.y);
            as[nxt][ka + 2][arow] = f2tf(pa0.z + pl0.z); as[nxt][ka + 3][arow] = f2tf(pa0.w + pl0.w);
            as[nxt][ka + 4][arow] = f2tf(pa1.x + pl1.x); as[nxt][ka + 5][arow] = f2tf(pa1.y + pl1.y);
            as[nxt][ka + 6][arow] = f2tf(pa1.z + pl1.z); as[nxt][ka + 7][arow] = f2tf(pa1.w + pl1.w);
            uint4 u0 = {f2tf(pb0.x), f2tf(pb0.y), f2tf(pb0.z), f2tf(pb0.w)};
            uint4 u1 = {f2tf(pb1.x), f2tf(pb1.y), f2tf(pb1.z), f2tf(pb1.w)};
            *(uint4*)&bs[nxt][brow][bq]     = u0;
            *(uint4*)&bs[nxt][brow][bq + 4] = u1;
            __syncthreads();
            cur = nxt;
        }
    }

    // epilogue: image-layout writes with bias
    int c2 = c * 2;
    float2 bb[4];
#pragma unroll
    for (int nt = 0; nt < 4; nt++)
        bb[nt] = *(const float2*)&bo[n0 + wn * 32 + nt * 8 + c2];
#pragma unroll
    for (int mt = 0; mt < 4; mt++) {
#pragma unroll
        for (int h = 0; h < 2; h++) {
            int mm = m0 + wm * 64 + mt * 16 + r + h * 8;
            int bbx = mm / 3136, rr = mm % 3136;
            int pp = rr >> 6, px = rr & 63;
            int yy = (pp / NW) * WS + (px >> 3);
            int xq = (pp % NW) * WS + (px & 7);
            float* orow = out + (size_t)(bbx * 3136 + yy * WDIM + xq) * CC
                        + n0 + wn * 32 + c2;
#pragma unroll
            for (int nt = 0; nt < 4; nt++) {
                float4 a = acc[mt][nt];
                float2 o;
                o.x = (h ? a.z : a.x) + bb[nt].x;
                o.y = (h ? a.w : a.y) + bb[nt].y;
                *(float2*)(orow + nt * 8) = o;
            }
        }
    }
}

// ---------------------------------------------------------------------------
extern "C" void kernel_launch(void* const* d_in, const int* in_sizes, int n_in,
                              void* d_out, int out_size)
{
    const float* x      = (const float*)d_in[0];
    const float* Wqkv   = (const float*)d_in[1];
    const float* bqkv   = (const float*)d_in[2];
    const float* Wo     = (const float*)d_in[3];
    const float* bo     = (const float*)d_in[4];
    const float* lepe_w = (const float*)d_in[5];
    const float* lepe_b = (const float*)d_in[6];
    float* out = (float*)d_out;

    cudaFuncSetAttribute(attn_kernel,
                         cudaFuncAttributeMaxDynamicSharedMemorySize,
                         SM_FLOATS * 4);

    gemm_qkv_tc<<<dim3(MTOT / 128, QKVW / 128), 256>>>(x, Wqkv, bqkv);
    win_mean_kernel<<<BB * P2, 256>>>();
    routing_kernel<<<BB * P2, 256>>>();
    lepe_kernel<<<BB * P2 * 4, 256>>>(lepe_w, lepe_b);
    attn_kernel<<<BB * P2 * NHEAD, 256, SM_FLOATS * 4>>>();
    gemm_out_tc<<<dim3(MTOT / 128, CC / 128), 256>>>(Wo, bo, out);
}

// round 11
// speedup vs baseline: 2.2709x; 1.4952x over previous
#include <cuda_runtime.h>
#include <cuda_bf16.h>
#include <cstdint>

// Problem constants
#define BB    4
#define HDIM  56
#define WDIM  56
#define CC    256
#define NW    7
#define WS    8
#define P2    49
#define PIX   64
#define NHEAD 8
#define HDH   32
#define TOPK  4
#define MTOT  (BB * P2 * PIX)      // 12544 == BB*HDIM*WDIM
#define QKVW  768
#define SCALE 0.0625f              // 256^-0.5

// Scratch (window-ordered where noted)
__device__ float g_qkv[(size_t)MTOT * QKVW];       // (b,p,pix, 768): q|k|v
__device__ float g_qwin[BB * P2 * CC];
__device__ float g_kwin[BB * P2 * CC];
__device__ int   g_ridx[BB * P2 * TOPK];
__device__ float g_lepe[(size_t)BB * HDIM * WDIM * CC];   // image layout
__device__ float g_aout[(size_t)MTOT * CC];               // window layout

// ---------------------------------------------------------------------------
// tf32 helpers
// ---------------------------------------------------------------------------
__device__ __forceinline__ uint32_t f2tf(float f) {
    uint32_t u;
    asm("cvt.rna.tf32.f32 %0, %1;" : "=r"(u) : "f"(f));
    return u;
}

__device__ __forceinline__ void mma_tf32(float4& d, const uint32_t a[4],
                                         const uint32_t b[2]) {
    asm volatile(
        "mma.sync.aligned.m16n8k8.row.col.f32.tf32.tf32.f32 "
        "{%0,%1,%2,%3},{%4,%5,%6,%7},{%8,%9},{%0,%1,%2,%3};"
        : "+f"(d.x), "+f"(d.y), "+f"(d.z), "+f"(d.w)
        : "r"(a[0]), "r"(a[1]), "r"(a[2]), "r"(a[3]), "r"(b[0]), "r"(b[1]));
}

#define BK    16
#define ASTR  136

// ---------------------------------------------------------------------------
// Kernel 1: QKV GEMM via tf32 tensor cores. (unchanged from R10)
// ---------------------------------------------------------------------------
__global__ __launch_bounds__(256) void gemm_qkv_tc(
    const float* __restrict__ x, const float* __restrict__ Wqkv,
    const float* __restrict__ bqkv)
{
    __shared__ uint32_t as[2][BK][ASTR];   // [k][m]
    __shared__ uint32_t bs[2][BK][ASTR];   // [k][n]
    int t = threadIdx.x;
    int warp = t >> 5, lane = t & 31;
    int wm = warp >> 2, wn = warp & 3;
    int m0 = blockIdx.x * 128;
    int n0 = blockIdx.y * 128;

    int arow = t & 127;
    int ka   = (t >> 7) * 8;
    {
        int m = m0 + arow;
        int b = m / 3136, r2 = m % 3136;
        int p = r2 >> 6, pix = r2 & 63;
        int y  = (p / NW) * WS + (pix >> 3);
        int xx = (p % NW) * WS + (pix & 7);
        x += (size_t)(b * 3136 + y * WDIM + xx) * CC;
    }
    int brow = t >> 4;
    int bq   = (t & 15) * 8;

    float4 acc[4][4];
#pragma unroll
    for (int i = 0; i < 4; i++)
#pragma unroll
        for (int j = 0; j < 4; j++) acc[i][j] = make_float4(0.f, 0.f, 0.f, 0.f);

    {
        float4 a0 = *(const float4*)(x + ka);
        float4 a1 = *(const float4*)(x + ka + 4);
        float4 b0 = *(const float4*)(Wqkv + (size_t)brow * QKVW + n0 + bq);
        float4 b1 = *(const float4*)(Wqkv + (size_t)brow * QKVW + n0 + bq + 4);
        as[0][ka + 0][arow] = f2tf(a0.x); as[0][ka + 1][arow] = f2tf(a0.y);
        as[0][ka + 2][arow] = f2tf(a0.z); as[0][ka + 3][arow] = f2tf(a0.w);
        as[0][ka + 4][arow] = f2tf(a1.x); as[0][ka + 5][arow] = f2tf(a1.y);
        as[0][ka + 6][arow] = f2tf(a1.z); as[0][ka + 7][arow] = f2tf(a1.w);
        uint4 u0 = {f2tf(b0.x), f2tf(b0.y), f2tf(b0.z), f2tf(b0.w)};
        uint4 u1 = {f2tf(b1.x), f2tf(b1.y), f2tf(b1.z), f2tf(b1.w)};
        *(uint4*)&bs[0][brow][bq]     = u0;
        *(uint4*)&bs[0][brow][bq + 4] = u1;
    }
    __syncthreads();

    int r = lane >> 2, c = lane & 3;
    int cur = 0;
    for (int k0 = 0; k0 < CC; k0 += BK) {
        bool more = (k0 + BK < CC);
        float4 pa0, pa1, pb0, pb1;
        if (more) {
            pa0 = *(const float4*)(x + k0 + BK + ka);
            pa1 = *(const float4*)(x + k0 + BK + ka + 4);
            pb0 = *(const float4*)(Wqkv + (size_t)(k0 + BK + brow) * QKVW + n0 + bq);
            pb1 = *(const float4*)(Wqkv + (size_t)(k0 + BK + brow) * QKVW + n0 + bq + 4);
        }
#pragma unroll
        for (int kc = 0; kc < 2; kc++) {
            int kb = kc * 8;
            uint32_t bf[4][2];
#pragma unroll
            for (int nt = 0; nt < 4; nt++) {
                int n = wn * 32 + nt * 8 + r;
                bf[nt][0] = bs[cur][kb + c][n];
                bf[nt][1] = bs[cur][kb + 4 + c][n];
            }
#pragma unroll
            for (int mt = 0; mt < 4; mt++) {
                int m = wm * 64 + mt * 16;
                uint32_t af[4];
                af[0] = as[cur][kb + c][m + r];
                af[1] = as[cur][kb + c][m + r + 8];
                af[2] = as[cur][kb + 4 + c][m + r];
                af[3] = as[cur][kb + 4 + c][m + r + 8];
#pragma unroll
                for (int nt = 0; nt < 4; nt++) mma_tf32(acc[mt][nt], af, bf[nt]);
            }
        }
        if (more) {
            int nxt = cur ^ 1;
            as[nxt][ka + 0][arow] = f2tf(pa0.x); as[nxt][ka + 1][arow] = f2tf(pa0.y);
            as[nxt][ka + 2][arow] = f2tf(pa0.z); as[nxt][ka + 3][arow] = f2tf(pa0.w);
            as[nxt][ka + 4][arow] = f2tf(pa1.x); as[nxt][ka + 5][arow] = f2tf(pa1.y);
            as[nxt][ka + 6][arow] = f2tf(pa1.z); as[nxt][ka + 7][arow] = f2tf(pa1.w);
            uint4 u0 = {f2tf(pb0.x), f2tf(pb0.y), f2tf(pb0.z), f2tf(pb0.w)};
            uint4 u1 = {f2tf(pb1.x), f2tf(pb1.y), f2tf(pb1.z), f2tf(pb1.w)};
            *(uint4*)&bs[nxt][brow][bq]     = u0;
            *(uint4*)&bs[nxt][brow][bq + 4] = u1;
            __syncthreads();
            cur = nxt;
        }
    }

    int c2 = c * 2;
#pragma unroll
    for (int nt = 0; nt < 4; nt++) {
        int col = n0 + wn * 32 + nt * 8 + c2;
        float2 bb = *(const float2*)&bqkv[col];
#pragma unroll
        for (int mt = 0; mt < 4; mt++) {
            int mm = m0 + wm * 64 + mt * 16 + r;
            float4 a = acc[mt][nt];
            float2 o0 = {a.x + bb.x, a.y + bb.y};
            float2 o1 = {a.z + bb.x, a.w + bb.y};
            *(float2*)(g_qkv + (size_t)mm * QKVW + col) = o0;
            *(float2*)(g_qkv + (size_t)(mm + 8) * QKVW + col) = o1;
        }
    }
}

// ---------------------------------------------------------------------------
// Kernel 2: per-window means of q and k
// ---------------------------------------------------------------------------
__global__ void win_mean_kernel()
{
    int bp = blockIdx.x;
    int c = threadIdx.x;
    const float* base = g_qkv + (size_t)bp * PIX * QKVW;
    float sq = 0.f, sk = 0.f;
#pragma unroll 4
    for (int px = 0; px < PIX; px++) {
        sq += base[px * QKVW + c];
        sk += base[px * QKVW + CC + c];
    }
    g_qwin[bp * CC + c] = sq * (1.f / 64.f);
    g_kwin[bp * CC + c] = sk * (1.f / 64.f);
}

// ---------------------------------------------------------------------------
// Kernel 3: routing logits + top-4
// ---------------------------------------------------------------------------
__global__ __launch_bounds__(256) void routing_kernel()
{
    __shared__ float lg[P2];
    __shared__ float qsh[CC];
    int b = blockIdx.x / P2;
    int p = blockIdx.x % P2;
    int t = threadIdx.x;
    qsh[t] = g_qwin[(size_t)(b * P2 + p) * CC + t];
    __syncthreads();
    int w = t >> 5, lane = t & 31;
    for (int j = w; j < P2; j += 8) {
        const float* kr = g_kwin + (size_t)(b * P2 + j) * CC;
        float s = 0.f;
#pragma unroll
        for (int cb = 0; cb < CC; cb += 32) s += qsh[cb + lane] * kr[cb + lane];
#pragma unroll
        for (int o = 16; o; o >>= 1) s += __shfl_xor_sync(0xffffffffu, s, o);
        if (lane == 0) lg[j] = s;
    }
    __syncthreads();
    if (t == 0) {
        for (int s = 0; s < TOPK; s++) {
            float best = -1e30f; int bi = 0;
            for (int j = 0; j < P2; j++)
                if (lg[j] > best) { best = lg[j]; bi = j; }
            g_ridx[(b * P2 + p) * TOPK + s] = bi;
            lg[bi] = -1e30f;
        }
    }
}

// ---------------------------------------------------------------------------
// Kernel 4: lepe = depthwise 5x5 conv over v (halo-tile version)
// ---------------------------------------------------------------------------
__global__ __launch_bounds__(256) void lepe_kernel(
    const float* __restrict__ lw, const float* __restrict__ lb)
{
    __shared__ float halo[144 * 64];
    int blk = blockIdx.x;
    int cq = blk & 3;
    int bp = blk >> 2;
    int b = bp / P2, p = bp % P2;
    int y0 = (p / NW) * WS - 2;
    int x0 = (p % NW) * WS - 2;
    int t = threadIdx.x;

#pragma unroll
    for (int i = 0; i < 9; i++) {
        int f = t + i * 256;
        int pix = f >> 4;
        int q4 = (f & 15) * 4;
        int hy = pix / 12, hx = pix % 12;
        int yy = y0 + hy, xs = x0 + hx;
        float4 v = {0.f, 0.f, 0.f, 0.f};
        if (yy >= 0 && yy < HDIM && xs >= 0 && xs < WDIM) {
            int sp = (yy >> 3) * NW + (xs >> 3);
            int spx = ((yy & 7) << 3) + (xs & 7);
            v = *(const float4*)(g_qkv +
                (size_t)((b * P2 + sp) * PIX + spx) * QKVW + 2 * CC + cq * 64 + q4);
        }
        *(float4*)&halo[pix * 64 + q4] = v;
    }

    int c = t & 63;
    int gc = cq * 64 + c;
    float wr[25];
#pragma unroll
    for (int k = 0; k < 25; k++) wr[k] = lw[k * CC + gc];
    float bias = lb[gc];
    __syncthreads();

    int tp = t >> 6;
#pragma unroll
    for (int u = 0; u < 16; u++) {
        int p8 = tp * 16 + u;
        int ly = p8 >> 3, lx = p8 & 7;
        float acc = bias;
#pragma unroll
        for (int dy = 0; dy < 5; dy++)
#pragma unroll
            for (int dx = 0; dx < 5; dx++)
                acc += halo[((ly + dy) * 12 + (lx + dx)) * 64 + c] * wr[dy * 5 + dx];
        g_lepe[((size_t)b * 3136 + (y0 + 2 + ly) * WDIM + (x0 + 2 + lx)) * CC + gc] = acc;
    }
}

// ---------------------------------------------------------------------------
// Kernel 5: attention per (b, window, head) — tf32 tensor cores.
// Stage 1: S = (Q*scale) K^T via mma (M=64, N=256, K=32), warp w owns keys
//          w*32..w*32+31.
// Softmax: 4 threads per q-row, strided key partition (bank-friendly).
// Stage 2: O = P V via mma (M=64, N=32, K=256), k-split across warp pairs,
//          smem reduction (reuses dead Q region).
// smem word offsets (floats/uint32):
//   qs 32x72 tf32     @ 0      (2304)   [dead after stage 1 -> red buffer]
//   ks 32x264 tf32    @ 2304   (8448)
//   vs 256x40 tf32    @ 10752  (10240)
//   sc 64x264 f32     @ 20992  (16896)
//   pmax 256          @ 37888
//   psum 256          @ 38144
//   total 38400 words = 153600 B
// ---------------------------------------------------------------------------
#define AT_QS   0
#define AT_KS   2304
#define AT_VS   10752
#define AT_SC   20992
#define AT_PM   37888
#define AT_PS   38144
#define AT_WORDS 38400
#define QSTR  72
#define KSTR  264
#define VSTR  40
#define SSTR  264
#define RSTR  33

__global__ __launch_bounds__(256) void attn_tc_kernel()
{
    extern __shared__ float sm[];
    uint32_t* qs = (uint32_t*)(sm + AT_QS);
    uint32_t* ks = (uint32_t*)(sm + AT_KS);
    uint32_t* vs = (uint32_t*)(sm + AT_VS);
    float*    sc = sm + AT_SC;
    float*  pmax = sm + AT_PM;
    float*  psum = sm + AT_PS;
    float*   red = sm + AT_QS;   // aliases qs (dead after stage 1)

    int blk = blockIdx.x;
    int b  = blk / (P2 * NHEAD);
    int p  = (blk / NHEAD) % P2;
    int hh = blk % NHEAD;
    int bp = b * P2 + p;
    int t = threadIdx.x;
    int w = t >> 5, lane = t & 31;
    int r = lane >> 2, c = lane & 3;

    int widx[TOPK];
#pragma unroll
    for (int s = 0; s < TOPK; s++) widx[s] = g_ridx[bp * TOPK + s];

    // ---- load Q (scaled, transposed): qs[k][px] ----
    {
        int px = t & 63;
        int kq = (t >> 6) * 8;
        const float* qb = g_qkv + (size_t)(bp * PIX + px) * QKVW + hh * HDH + kq;
        float4 v0 = *(const float4*)qb;
        float4 v1 = *(const float4*)(qb + 4);
        qs[(kq + 0) * QSTR + px] = f2tf(v0.x * SCALE);
        qs[(kq + 1) * QSTR + px] = f2tf(v0.y * SCALE);
        qs[(kq + 2) * QSTR + px] = f2tf(v0.z * SCALE);
        qs[(kq + 3) * QSTR + px] = f2tf(v0.w * SCALE);
        qs[(kq + 4) * QSTR + px] = f2tf(v1.x * SCALE);
        qs[(kq + 5) * QSTR + px] = f2tf(v1.y * SCALE);
        qs[(kq + 6) * QSTR + px] = f2tf(v1.z * SCALE);
        qs[(kq + 7) * QSTR + px] = f2tf(v1.w * SCALE);
    }

    // ---- load K (transposed): ks[k][key], key = t ----
    {
        int s = t >> 6, loc = t & 63;
        const float* kb = g_qkv + (size_t)((b * P2 + widx[s]) * PIX + loc) * QKVW
                        + CC + hh * HDH;
#pragma unroll
        for (int d4 = 0; d4 < 8; d4++) {
            float4 v = *(const float4*)(kb + d4 * 4);
            ks[(d4 * 4 + 0) * KSTR + t] = f2tf(v.x);
            ks[(d4 * 4 + 1) * KSTR + t] = f2tf(v.y);
            ks[(d4 * 4 + 2) * KSTR + t] = f2tf(v.z);
            ks[(d4 * 4 + 3) * KSTR + t] = f2tf(v.w);
        }
    }

    // ---- load V: vs[key][dim] ----
    {
        int d4 = (t & 7) * 4;
        int krow = t >> 3;            // 0..31
#pragma unroll
        for (int pass = 0; pass < 8; pass++) {
            int key = pass * 32 + krow;
            int s = key >> 6, loc = key & 63;
            float4 v = *(const float4*)(g_qkv +
                (size_t)((b * P2 + widx[s]) * PIX + loc) * QKVW + 2 * CC
                + hh * HDH + d4);
            uint4 u = {f2tf(v.x), f2tf(v.y), f2tf(v.z), f2tf(v.w)};
            *(uint4*)&vs[key * VSTR + d4] = u;
        }
    }
    __syncthreads();

    // ---- stage 1: S = Q K^T ----
    {
        float4 acc1[4][4];
#pragma unroll
        for (int i = 0; i < 4; i++)
#pragma unroll
            for (int j = 0; j < 4; j++) acc1[i][j] = make_float4(0.f, 0.f, 0.f, 0.f);

#pragma unroll
        for (int ks8 = 0; ks8 < 4; ks8++) {
            int kb = ks8 * 8;
            uint32_t bf[4][2];
#pragma unroll
            for (int nt = 0; nt < 4; nt++) {
                int n = w * 32 + nt * 8 + r;
                bf[nt][0] = ks[(kb + c) * KSTR + n];
                bf[nt][1] = ks[(kb + 4 + c) * KSTR + n];
            }
#pragma unroll
            for (int mt = 0; mt < 4; mt++) {
                int m = mt * 16;
                uint32_t af[4];
                af[0] = qs[(kb + c) * QSTR + m + r];
                af[1] = qs[(kb + c) * QSTR + m + r + 8];
                af[2] = qs[(kb + 4 + c) * QSTR + m + r];
                af[3] = qs[(kb + 4 + c) * QSTR + m + r + 8];
#pragma unroll
                for (int nt = 0; nt < 4; nt++) mma_tf32(acc1[mt][nt], af, bf[nt]);
            }
        }
        // store S to smem
        int c2 = c * 2;
#pragma unroll
        for (int mt = 0; mt < 4; mt++) {
#pragma unroll
            for (int nt = 0; nt < 4; nt++) {
                int col = w * 32 + nt * 8 + c2;
                float4 a = acc1[mt][nt];
                *(float2*)&sc[(mt * 16 + r) * SSTR + col]     = make_float2(a.x, a.y);
                *(float2*)&sc[(mt * 16 + r + 8) * SSTR + col] = make_float2(a.z, a.w);
            }
        }
    }
    __syncthreads();

    // ---- softmax: 4 threads per row, strided key partition ----
    {
        int part = t & 3;
        int qi = t >> 2;
        float* row = sc + qi * SSTR;
        float mx = -1e30f;
#pragma unroll 8
        for (int j = 0; j < 64; j++) mx = fmaxf(mx, row[part + 4 * j]);
        pmax[qi * 4 + part] = mx;
        __syncthreads();
        float rm = fmaxf(fmaxf(pmax[qi * 4], pmax[qi * 4 + 1]),
                         fmaxf(pmax[qi * 4 + 2], pmax[qi * 4 + 3]));
        float s = 0.f;
#pragma unroll 8
        for (int j = 0; j < 64; j++) {
            float e = __expf(row[part + 4 * j] - rm);
            row[part + 4 * j] = e;
            s += e;
        }
        psum[qi * 4 + part] = s;
        __syncthreads();
        float inv = 1.f / (psum[qi * 4] + psum[qi * 4 + 1] +
                           psum[qi * 4 + 2] + psum[qi * 4 + 3]);
#pragma unroll 8
        for (int j = 0; j < 64; j++) row[part + 4 * j] *= inv;
    }
    __syncthreads();

    // ---- stage 2: O = P V, k-split across warp pairs ----
    {
        int mt2 = w & 3;
        int khalf = w >> 2;
        int m0 = mt2 * 16;
        float4 acc2[4];
#pragma unroll
        for (int nt = 0; nt < 4; nt++) acc2[nt] = make_float4(0.f, 0.f, 0.f, 0.f);

#pragma unroll 4
        for (int ks8 = 0; ks8 < 16; ks8++) {
            int kb = khalf * 128 + ks8 * 8;
            uint32_t af[4];
            af[0] = f2tf(sc[(m0 + r) * SSTR + kb + c]);
            af[1] = f2tf(sc[(m0 + r + 8) * SSTR + kb + c]);
            af[2] = f2tf(sc[(m0 + r) * SSTR + kb + c + 4]);
            af[3] = f2tf(sc[(m0 + r + 8) * SSTR + kb + c + 4]);
#pragma unroll
            for (int nt = 0; nt < 4; nt++) {
                uint32_t bf[2];
                bf[0] = vs[(kb + c) * VSTR + nt * 8 + r];
                bf[1] = vs[(kb + 4 + c) * VSTR + nt * 8 + r];
                mma_tf32(acc2[nt], af, bf);
            }
        }

        int c2 = c * 2;
        if (w >= 4) {
            float* rb = red + mt2 * (16 * RSTR);
#pragma unroll
            for (int nt = 0; nt < 4; nt++) {
                int col = nt * 8 + c2;
                rb[r * RSTR + col]           = acc2[nt].x;
                rb[r * RSTR + col + 1]       = acc2[nt].y;
                rb[(r + 8) * RSTR + col]     = acc2[nt].z;
                rb[(r + 8) * RSTR + col + 1] = acc2[nt].w;
            }
        }
        __syncthreads();
        if (w < 4) {
            const float* rb = red + mt2 * (16 * RSTR);
#pragma unroll
            for (int nt = 0; nt < 4; nt++) {
                int col = nt * 8 + c2;
                float2 o0 = {acc2[nt].x + rb[r * RSTR + col],
                             acc2[nt].y + rb[r * RSTR + col + 1]};
                float2 o1 = {acc2[nt].z + rb[(r + 8) * RSTR + col],
                             acc2[nt].w + rb[(r + 8) * RSTR + col + 1]};
                *(float2*)(g_aout + (size_t)(bp * PIX + m0 + r) * CC
                           + hh * HDH + col) = o0;
                *(float2*)(g_aout + (size_t)(bp * PIX + m0 + r + 8) * CC
                           + hh * HDH + col) = o1;
            }
        }
    }
}

// ---------------------------------------------------------------------------
// Kernel 6: out = (attn_out + lepe) @ Wo + bo via tf32 tensor cores.
// ---------------------------------------------------------------------------
__global__ __launch_bounds__(256) void gemm_out_tc(
    const float* __restrict__ Wo, const float* __restrict__ bo,
    float* __restrict__ out)
{
    __shared__ uint32_t as[2][BK][ASTR];
    __shared__ uint32_t bs[2][BK][ASTR];
    int t = threadIdx.x;
    int warp = t >> 5, lane = t & 31;
    int wm = warp >> 2, wn = warp & 3;
    int m0 = blockIdx.x * 128;
    int n0 = blockIdx.y * 128;

    int arow = t & 127;
    int ka   = (t >> 7) * 8;
    const float* ap;
    const float* lp;
    {
        int m = m0 + arow;
        int b = m / 3136, r2 = m % 3136;
        int p = r2 >> 6, pix = r2 & 63;
        int y  = (p / NW) * WS + (pix >> 3);
        int xx = (p % NW) * WS + (pix & 7);
        lp = g_lepe + (size_t)(b * 3136 + y * WDIM + xx) * CC;
        ap = g_aout + (size_t)m * CC;
    }
    int brow = t >> 4;
    int bq   = (t & 15) * 8;

    float4 acc[4][4];
#pragma unroll
    for (int i = 0; i < 4; i++)
#pragma unroll
        for (int j = 0; j < 4; j++) acc[i][j] = make_float4(0.f, 0.f, 0.f, 0.f);

    {
        float4 a0 = *(const float4*)(ap + ka);
        float4 a1 = *(const float4*)(ap + ka + 4);
        float4 l0 = *(const float4*)(lp + ka);
        float4 l1 = *(const float4*)(lp + ka + 4);
        float4 b0 = *(const float4*)(Wo + (size_t)brow * CC + n0 + bq);
        float4 b1 = *(const float4*)(Wo + (size_t)brow * CC + n0 + bq + 4);
        as[0][ka + 0][arow] = f2tf(a0.x + l0.x); as[0][ka + 1][arow] = f2tf(a0.y + l0.y);
        as[0][ka + 2][arow] = f2tf(a0.z + l0.z); as[0][ka + 3][arow] = f2tf(a0.w + l0.w);
        as[0][ka + 4][arow] = f2tf(a1.x + l1.x); as[0][ka + 5][arow] = f2tf(a1.y + l1.y);
        as[0][ka + 6][arow] = f2tf(a1.z + l1.z); as[0][ka + 7][arow] = f2tf(a1.w + l1.w);
        uint4 u0 = {f2tf(b0.x), f2tf(b0.y), f2tf(b0.z), f2tf(b0.w)};
        uint4 u1 = {f2tf(b1.x), f2tf(b1.y), f2tf(b1.z), f2tf(b1.w)};
        *(uint4*)&bs[0][brow][bq]     = u0;
        *(uint4*)&bs[0][brow][bq + 4] = u1;
    }
    __syncthreads();

    int r = lane >> 2, c = lane & 3;
    int cur = 0;
    for (int k0 = 0; k0 < CC; k0 += BK) {
        bool more = (k0 + BK < CC);
        float4 pa0, pa1, pl0, pl1, pb0, pb1;
        if (more) {
            pa0 = *(const float4*)(ap + k0 + BK + ka);
            pa1 = *(const float4*)(ap + k0 + BK + ka + 4);
            pl0 = *(const float4*)(lp + k0 + BK + ka);
            pl1 = *(const float4*)(lp + k0 + BK + ka + 4);
            pb0 = *(const float4*)(Wo + (size_t)(k0 + BK + brow) * CC + n0 + bq);
            pb1 = *(const float4*)(Wo + (size_t)(k0 + BK + brow) * CC + n0 + bq + 4);
        }
#pragma unroll
        for (int kc = 0; kc < 2; kc++) {
            int kb = kc * 8;
            uint32_t bf[4][2];
#pragma unroll
            for (int nt = 0; nt < 4; nt++) {
                int n = wn * 32 + nt * 8 + r;
                bf[nt][0] = bs[cur][kb + c][n];
                bf[nt][1] = bs[cur][kb + 4 + c][n];
            }
#pragma unroll
            for (int mt = 0; mt < 4; mt++) {
                int m = wm * 64 + mt * 16;
                uint32_t af[4];
                af[0] = as[cur][kb + c][m + r];
                af[1] = as[cur][kb + c][m + r + 8];
                af[2] = as[cur][kb + 4 + c][m + r];
                af[3] = as[cur][kb + 4 + c][m + r + 8];
#pragma unroll
                for (int nt = 0; nt < 4; nt++) mma_tf32(acc[mt][nt], af, bf[nt]);
            }
        }
        if (more) {
            int nxt = cur ^ 1;
            as[nxt][ka + 0][arow] = f2tf(pa0.x + pl0.x); as[nxt][ka + 1][arow] = f2tf(pa0.y + pl0.y);
            as[nxt][ka + 2][arow] = f2tf(pa0.z + pl0.z); as[nxt][ka + 3][arow] = f2tf(pa0.w + pl0.w);
            as[nxt][ka + 4][arow] = f2tf(pa1.x + pl1.x); as[nxt][ka + 5][arow] = f2tf(pa1.y + pl1.y);
            as[nxt][ka + 6][arow] = f2tf(pa1.z + pl1.z); as[nxt][ka + 7][arow] = f2tf(pa1.w + pl1.w);
            uint4 u0 = {f2tf(pb0.x), f2tf(pb0.y), f2tf(pb0.z), f2tf(pb0.w)};
            uint4 u1 = {f2tf(pb1.x), f2tf(pb1.y), f2tf(pb1.z), f2tf(pb1.w)};
            *(uint4*)&bs[nxt][brow][bq]     = u0;
            *(uint4*)&bs[nxt][brow][bq + 4] = u1;
            __syncthreads();
            cur = nxt;
        }
    }

    int c2 = c * 2;
    float2 bb[4];
#pragma unroll
    for (int nt = 0; nt < 4; nt++)
        bb[nt] = *(const float2*)&bo[n0 + wn * 32 + nt * 8 + c2];
#pragma unroll
    for (int mt = 0; mt < 4; mt++) {
#pragma unroll
        for (int h = 0; h < 2; h++) {
            int mm = m0 + wm * 64 + mt * 16 + r + h * 8;
            int bbx = mm / 3136, rr = mm % 3136;
            int pp = rr >> 6, px = rr & 63;
            int yy = (pp / NW) * WS + (px >> 3);
            int xq = (pp % NW) * WS + (px & 7);
            float* orow = out + (size_t)(bbx * 3136 + yy * WDIM + xq) * CC
                        + n0 + wn * 32 + c2;
#pragma unroll
            for (int nt = 0; nt < 4; nt++) {
                float4 a = acc[mt][nt];
                float2 o;
                o.x = (h ? a.z : a.x) + bb[nt].x;
                o.y = (h ? a.w : a.y) + bb[nt].y;
                *(float2*)(orow + nt * 8) = o;
            }
        }
    }
}

// ---------------------------------------------------------------------------
extern "C" void kernel_launch(void* const* d_in, const int* in_sizes, int n_in,
                              void* d_out, int out_size)
{
    const float* x      = (const float*)d_in[0];
    const float* Wqkv   = (const float*)d_in[1];
    const float* bqkv   = (const float*)d_in[2];
    const float* Wo     = (const float*)d_in[3];
    const float* bo     = (const float*)d_in[4];
    const float* lepe_w = (const float*)d_in[5];
    const float* lepe_b = (const float*)d_in[6];
    float* out = (float*)d_out;

    cudaFuncSetAttribute(attn_tc_kernel,
                         cudaFuncAttributeMaxDynamicSharedMemorySize,
                         AT_WORDS * 4);

    gemm_qkv_tc<<<dim3(MTOT / 128, QKVW / 128), 256>>>(x, Wqkv, bqkv);
    win_mean_kernel<<<BB * P2, 256>>>();
    routing_kernel<<<BB * P2, 256>>>();
    lepe_kernel<<<BB * P2 * 4, 256>>>(lepe_w, lepe_b);
    attn_tc_kernel<<<BB * P2 * NHEAD, 256, AT_WORDS * 4>>>();
    gemm_out_tc<<<dim3(MTOT / 128, CC / 128), 256>>>(Wo, bo, out);
}

// round 12
// speedup vs baseline: 2.3484x; 1.0341x over previous
#include <cuda_runtime.h>
#include <cuda_bf16.h>
#include <cstdint>

// Problem constants
#define BB    4
#define HDIM  56
#define WDIM  56
#define CC    256
#define NW    7
#define WS    8
#define P2    49
#define PIX   64
#define NHEAD 8
#define HDH   32
#define TOPK  4
#define MTOT  (BB * P2 * PIX)      // 12544 == BB*HDIM*WDIM
#define QKVW  768
#define SCALE 0.0625f              // 256^-0.5

// Scratch (window-ordered where noted)
__device__ float g_qkv[(size_t)MTOT * QKVW];       // (b,p,pix, 768): q|k|v
__device__ float g_qwin[BB * P2 * CC];
__device__ float g_kwin[BB * P2 * CC];
__device__ int   g_ridx[BB * P2 * TOPK];
__device__ float g_lepe[(size_t)BB * HDIM * WDIM * CC];   // image layout
__device__ float g_aout[(size_t)MTOT * CC];               // window layout

// ---------------------------------------------------------------------------
// tf32 helpers
// ---------------------------------------------------------------------------
__device__ __forceinline__ uint32_t f2tf(float f) {
    uint32_t u;
    asm("cvt.rna.tf32.f32 %0, %1;" : "=r"(u) : "f"(f));
    return u;
}

__device__ __forceinline__ void mma_tf32(float4& d, const uint32_t a[4],
                                         const uint32_t b[2]) {
    asm volatile(
        "mma.sync.aligned.m16n8k8.row.col.f32.tf32.tf32.f32 "
        "{%0,%1,%2,%3},{%4,%5,%6,%7},{%8,%9},{%0,%1,%2,%3};"
        : "+f"(d.x), "+f"(d.y), "+f"(d.z), "+f"(d.w)
        : "r"(a[0]), "r"(a[1]), "r"(a[2]), "r"(a[3]), "r"(b[0]), "r"(b[1]));
}

#define BK    16
#define ASTR  136

// ---------------------------------------------------------------------------
// Kernel 1: QKV GEMM via tf32 tensor cores, with fused per-window q/k means.
// 128x128 block, 8 warps (2x4), warp tile 64x32, m16n8k8 tiles.
// A 128-row block = exactly 2 windows (64 rows each); warp-half wm owns
// one window, so each thread's accumulators span all 64 rows of window
// (2*blockIdx.x + wm) for its column pairs -> shfl reduction gives means.
// ---------------------------------------------------------------------------
__global__ __launch_bounds__(256) void gemm_qkv_tc(
    const float* __restrict__ x, const float* __restrict__ Wqkv,
    const float* __restrict__ bqkv)
{
    __shared__ uint32_t as[2][BK][ASTR];   // [k][m]
    __shared__ uint32_t bs[2][BK][ASTR];   // [k][n]
    int t = threadIdx.x;
    int warp = t >> 5, lane = t & 31;
    int wm = warp >> 2, wn = warp & 3;
    int m0 = blockIdx.x * 128;
    int n0 = blockIdx.y * 128;

    int arow = t & 127;
    int ka   = (t >> 7) * 8;
    {
        int m = m0 + arow;
        int b = m / 3136, r2 = m % 3136;
        int p = r2 >> 6, pix = r2 & 63;
        int y  = (p / NW) * WS + (pix >> 3);
        int xx = (p % NW) * WS + (pix & 7);
        x += (size_t)(b * 3136 + y * WDIM + xx) * CC;
    }
    int brow = t >> 4;
    int bq   = (t & 15) * 8;

    float4 acc[4][4];
#pragma unroll
    for (int i = 0; i < 4; i++)
#pragma unroll
        for (int j = 0; j < 4; j++) acc[i][j] = make_float4(0.f, 0.f, 0.f, 0.f);

    {
        float4 a0 = *(const float4*)(x + ka);
        float4 a1 = *(const float4*)(x + ka + 4);
        float4 b0 = *(const float4*)(Wqkv + (size_t)brow * QKVW + n0 + bq);
        float4 b1 = *(const float4*)(Wqkv + (size_t)brow * QKVW + n0 + bq + 4);
        as[0][ka + 0][arow] = f2tf(a0.x); as[0][ka + 1][arow] = f2tf(a0.y);
        as[0][ka + 2][arow] = f2tf(a0.z); as[0][ka + 3][arow] = f2tf(a0.w);
        as[0][ka + 4][arow] = f2tf(a1.x); as[0][ka + 5][arow] = f2tf(a1.y);
        as[0][ka + 6][arow] = f2tf(a1.z); as[0][ka + 7][arow] = f2tf(a1.w);
        uint4 u0 = {f2tf(b0.x), f2tf(b0.y), f2tf(b0.z), f2tf(b0.w)};
        uint4 u1 = {f2tf(b1.x), f2tf(b1.y), f2tf(b1.z), f2tf(b1.w)};
        *(uint4*)&bs[0][brow][bq]     = u0;
        *(uint4*)&bs[0][brow][bq + 4] = u1;
    }
    __syncthreads();

    int r = lane >> 2, c = lane & 3;
    int cur = 0;
    for (int k0 = 0; k0 < CC; k0 += BK) {
        bool more = (k0 + BK < CC);
        float4 pa0, pa1, pb0, pb1;
        if (more) {
            pa0 = *(const float4*)(x + k0 + BK + ka);
            pa1 = *(const float4*)(x + k0 + BK + ka + 4);
            pb0 = *(const float4*)(Wqkv + (size_t)(k0 + BK + brow) * QKVW + n0 + bq);
            pb1 = *(const float4*)(Wqkv + (size_t)(k0 + BK + brow) * QKVW + n0 + bq + 4);
        }
#pragma unroll
        for (int kc = 0; kc < 2; kc++) {
            int kb = kc * 8;
            uint32_t bf[4][2];
#pragma unroll
            for (int nt = 0; nt < 4; nt++) {
                int n = wn * 32 + nt * 8 + r;
                bf[nt][0] = bs[cur][kb + c][n];
                bf[nt][1] = bs[cur][kb + 4 + c][n];
            }
#pragma unroll
            for (int mt = 0; mt < 4; mt++) {
                int m = wm * 64 + mt * 16;
                uint32_t af[4];
                af[0] = as[cur][kb + c][m + r];
                af[1] = as[cur][kb + c][m + r + 8];
                af[2] = as[cur][kb + 4 + c][m + r];
                af[3] = as[cur][kb + 4 + c][m + r + 8];
#pragma unroll
                for (int nt = 0; nt < 4; nt++) mma_tf32(acc[mt][nt], af, bf[nt]);
            }
        }
        if (more) {
            int nxt = cur ^ 1;
            as[nxt][ka + 0][arow] = f2tf(pa0.x); as[nxt][ka + 1][arow] = f2tf(pa0.y);
            as[nxt][ka + 2][arow] = f2tf(pa0.z); as[nxt][ka + 3][arow] = f2tf(pa0.w);
            as[nxt][ka + 4][arow] = f2tf(pa1.x); as[nxt][ka + 5][arow] = f2tf(pa1.y);
            as[nxt][ka + 6][arow] = f2tf(pa1.z); as[nxt][ka + 7][arow] = f2tf(pa1.w);
            uint4 u0 = {f2tf(pb0.x), f2tf(pb0.y), f2tf(pb0.z), f2tf(pb0.w)};
            uint4 u1 = {f2tf(pb1.x), f2tf(pb1.y), f2tf(pb1.z), f2tf(pb1.w)};
            *(uint4*)&bs[nxt][brow][bq]     = u0;
            *(uint4*)&bs[nxt][brow][bq + 4] = u1;
            __syncthreads();
            cur = nxt;
        }
    }

    int c2 = c * 2;
#pragma unroll
    for (int nt = 0; nt < 4; nt++) {
        int col = n0 + wn * 32 + nt * 8 + c2;
        float2 bb = *(const float2*)&bqkv[col];
#pragma unroll
        for (int mt = 0; mt < 4; mt++) {
            int mm = m0 + wm * 64 + mt * 16 + r;
            float4 a = acc[mt][nt];
            float2 o0 = {a.x + bb.x, a.y + bb.y};
            float2 o1 = {a.z + bb.x, a.w + bb.y};
            *(float2*)(g_qkv + (size_t)mm * QKVW + col) = o0;
            *(float2*)(g_qkv + (size_t)(mm + 8) * QKVW + col) = o1;
        }
    }

    // ---- fused window means (only q|k column blocks: n0 < 512) ----
    if (n0 < 512) {
        int win = 2 * blockIdx.x + wm;   // global (b*49+p) window index
#pragma unroll
        for (int nt = 0; nt < 4; nt++) {
            int col = n0 + wn * 32 + nt * 8 + c2;
            float s0 = 0.f, s1 = 0.f;
#pragma unroll
            for (int mt = 0; mt < 4; mt++) {
                float4 a = acc[mt][nt];
                s0 += a.x + a.z;
                s1 += a.y + a.w;
            }
            // reduce over the 8 lanes sharing column pair (r bits: 4,8,16)
#pragma unroll
            for (int o = 4; o <= 16; o <<= 1) {
                s0 += __shfl_xor_sync(0xffffffffu, s0, o);
                s1 += __shfl_xor_sync(0xffffffffu, s1, o);
            }
            if (r == 0) {
                float2 bb = *(const float2*)&bqkv[col];
                float m0v = s0 * (1.f / 64.f) + bb.x;
                float m1v = s1 * (1.f / 64.f) + bb.y;
                if (col < CC) {
                    g_qwin[(size_t)win * CC + col] = m0v;
                    g_qwin[(size_t)win * CC + col + 1] = m1v;
                } else {
                    g_kwin[(size_t)win * CC + col - CC] = m0v;
                    g_kwin[(size_t)win * CC + col - CC + 1] = m1v;
                }
            }
        }
    }
}

// ---------------------------------------------------------------------------
// Kernel 2: routing logits + top-4
// ---------------------------------------------------------------------------
__global__ __launch_bounds__(256) void routing_kernel()
{
    __shared__ float lg[P2];
    __shared__ float qsh[CC];
    int b = blockIdx.x / P2;
    int p = blockIdx.x % P2;
    int t = threadIdx.x;
    qsh[t] = g_qwin[(size_t)(b * P2 + p) * CC + t];
    __syncthreads();
    int w = t >> 5, lane = t & 31;
    for (int j = w; j < P2; j += 8) {
        const float* kr = g_kwin + (size_t)(b * P2 + j) * CC;
        float s = 0.f;
#pragma unroll
        for (int cb = 0; cb < CC; cb += 32) s += qsh[cb + lane] * kr[cb + lane];
#pragma unroll
        for (int o = 16; o; o >>= 1) s += __shfl_xor_sync(0xffffffffu, s, o);
        if (lane == 0) lg[j] = s;
    }
    __syncthreads();
    if (t == 0) {
        for (int s = 0; s < TOPK; s++) {
            float best = -1e30f; int bi = 0;
            for (int j = 0; j < P2; j++)
                if (lg[j] > best) { best = lg[j]; bi = j; }
            g_ridx[(b * P2 + p) * TOPK + s] = bi;
            lg[bi] = -1e30f;
        }
    }
}

// ---------------------------------------------------------------------------
// Kernel 3: lepe = depthwise 5x5 conv over v (halo-tile version)
// ---------------------------------------------------------------------------
__global__ __launch_bounds__(256) void lepe_kernel(
    const float* __restrict__ lw, const float* __restrict__ lb)
{
    __shared__ float halo[144 * 64];
    int blk = blockIdx.x;
    int cq = blk & 3;
    int bp = blk >> 2;
    int b = bp / P2, p = bp % P2;
    int y0 = (p / NW) * WS - 2;
    int x0 = (p % NW) * WS - 2;
    int t = threadIdx.x;

#pragma unroll
    for (int i = 0; i < 9; i++) {
        int f = t + i * 256;
        int pix = f >> 4;
        int q4 = (f & 15) * 4;
        int hy = pix / 12, hx = pix % 12;
        int yy = y0 + hy, xs = x0 + hx;
        float4 v = {0.f, 0.f, 0.f, 0.f};
        if (yy >= 0 && yy < HDIM && xs >= 0 && xs < WDIM) {
            int sp = (yy >> 3) * NW + (xs >> 3);
            int spx = ((yy & 7) << 3) + (xs & 7);
            v = *(const float4*)(g_qkv +
                (size_t)((b * P2 + sp) * PIX + spx) * QKVW + 2 * CC + cq * 64 + q4);
        }
        *(float4*)&halo[pix * 64 + q4] = v;
    }

    int c = t & 63;
    int gc = cq * 64 + c;
    float wr[25];
#pragma unroll
    for (int k = 0; k < 25; k++) wr[k] = lw[k * CC + gc];
    float bias = lb[gc];
    __syncthreads();

    int tp = t >> 6;
#pragma unroll
    for (int u = 0; u < 16; u++) {
        int p8 = tp * 16 + u;
        int ly = p8 >> 3, lx = p8 & 7;
        float acc = bias;
#pragma unroll
        for (int dy = 0; dy < 5; dy++)
#pragma unroll
            for (int dx = 0; dx < 5; dx++)
                acc += halo[((ly + dy) * 12 + (lx + dx)) * 64 + c] * wr[dy * 5 + dx];
        g_lepe[((size_t)b * 3136 + (y0 + 2 + ly) * WDIM + (x0 + 2 + lx)) * CC + gc] = acc;
    }
}

// ---------------------------------------------------------------------------
// Kernel 4: attention per (b, window, head) — tf32 tensor cores.
// P stored as tf32 bits in-place during softmax normalize (stage 2 loads raw).
// ---------------------------------------------------------------------------
#define AT_QS   0
#define AT_KS   2304
#define AT_VS   10752
#define AT_SC   20992
#define AT_PM   37888
#define AT_PS   38144
#define AT_WORDS 38400
#define QSTR  72
#define KSTR  264
#define VSTR  40
#define SSTR  264
#define RSTR  33

__global__ __launch_bounds__(256) void attn_tc_kernel()
{
    extern __shared__ float sm[];
    uint32_t* qs = (uint32_t*)(sm + AT_QS);
    uint32_t* ks = (uint32_t*)(sm + AT_KS);
    uint32_t* vs = (uint32_t*)(sm + AT_VS);
    float*    sc = sm + AT_SC;
    uint32_t* scu = (uint32_t*)sc;
    float*  pmax = sm + AT_PM;
    float*  psum = sm + AT_PS;
    float*   red = sm + AT_QS;   // aliases qs (dead after stage 1)

    int blk = blockIdx.x;
    int b  = blk / (P2 * NHEAD);
    int p  = (blk / NHEAD) % P2;
    int hh = blk % NHEAD;
    int bp = b * P2 + p;
    int t = threadIdx.x;
    int w = t >> 5, lane = t & 31;
    int r = lane >> 2, c = lane & 3;

    int widx[TOPK];
#pragma unroll
    for (int s = 0; s < TOPK; s++) widx[s] = g_ridx[bp * TOPK + s];

    // ---- load Q (scaled, transposed): qs[k][px] ----
    {
        int px = t & 63;
        int kq = (t >> 6) * 8;
        const float* qb = g_qkv + (size_t)(bp * PIX + px) * QKVW + hh * HDH + kq;
        float4 v0 = *(const float4*)qb;
        float4 v1 = *(const float4*)(qb + 4);
        qs[(kq + 0) * QSTR + px] = f2tf(v0.x * SCALE);
        qs[(kq + 1) * QSTR + px] = f2tf(v0.y * SCALE);
        qs[(kq + 2) * QSTR + px] = f2tf(v0.z * SCALE);
        qs[(kq + 3) * QSTR + px] = f2tf(v0.w * SCALE);
        qs[(kq + 4) * QSTR + px] = f2tf(v1.x * SCALE);
        qs[(kq + 5) * QSTR + px] = f2tf(v1.y * SCALE);
        qs[(kq + 6) * QSTR + px] = f2tf(v1.z * SCALE);
        qs[(kq + 7) * QSTR + px] = f2tf(v1.w * SCALE);
    }

    // ---- load K (transposed): ks[k][key], key = t ----
    {
        int s = t >> 6, loc = t & 63;
        const float* kb = g_qkv + (size_t)((b * P2 + widx[s]) * PIX + loc) * QKVW
                        + CC + hh * HDH;
#pragma unroll
        for (int d4 = 0; d4 < 8; d4++) {
            float4 v = *(const float4*)(kb + d4 * 4);
            ks[(d4 * 4 + 0) * KSTR + t] = f2tf(v.x);
            ks[(d4 * 4 + 1) * KSTR + t] = f2tf(v.y);
            ks[(d4 * 4 + 2) * KSTR + t] = f2tf(v.z);
            ks[(d4 * 4 + 3) * KSTR + t] = f2tf(v.w);
        }
    }

    // ---- load V: vs[key][dim] ----
    {
        int d4 = (t & 7) * 4;
        int krow = t >> 3;
#pragma unroll
        for (int pass = 0; pass < 8; pass++) {
            int key = pass * 32 + krow;
            int s = key >> 6, loc = key & 63;
            float4 v = *(const float4*)(g_qkv +
                (size_t)((b * P2 + widx[s]) * PIX + loc) * QKVW + 2 * CC
                + hh * HDH + d4);
            uint4 u = {f2tf(v.x), f2tf(v.y), f2tf(v.z), f2tf(v.w)};
            *(uint4*)&vs[key * VSTR + d4] = u;
        }
    }
    __syncthreads();

    // ---- stage 1: S = Q K^T ----
    {
        float4 acc1[4][4];
#pragma unroll
        for (int i = 0; i < 4; i++)
#pragma unroll
            for (int j = 0; j < 4; j++) acc1[i][j] = make_float4(0.f, 0.f, 0.f, 0.f);

#pragma unroll
        for (int ks8 = 0; ks8 < 4; ks8++) {
            int kb = ks8 * 8;
            uint32_t bf[4][2];
#pragma unroll
            for (int nt = 0; nt < 4; nt++) {
                int n = w * 32 + nt * 8 + r;
                bf[nt][0] = ks[(kb + c) * KSTR + n];
                bf[nt][1] = ks[(kb + 4 + c) * KSTR + n];
            }
#pragma unroll
            for (int mt = 0; mt < 4; mt++) {
                int m = mt * 16;
                uint32_t af[4];
                af[0] = qs[(kb + c) * QSTR + m + r];
                af[1] = qs[(kb + c) * QSTR + m + r + 8];
                af[2] = qs[(kb + 4 + c) * QSTR + m + r];
                af[3] = qs[(kb + 4 + c) * QSTR + m + r + 8];
#pragma unroll
                for (int nt = 0; nt < 4; nt++) mma_tf32(acc1[mt][nt], af, bf[nt]);
            }
        }
        int c2 = c * 2;
#pragma unroll
        for (int mt = 0; mt < 4; mt++) {
#pragma unroll
            for (int nt = 0; nt < 4; nt++) {
                int col = w * 32 + nt * 8 + c2;
                float4 a = acc1[mt][nt];
                *(float2*)&sc[(mt * 16 + r) * SSTR + col]     = make_float2(a.x, a.y);
                *(float2*)&sc[(mt * 16 + r + 8) * SSTR + col] = make_float2(a.z, a.w);
            }
        }
    }
    __syncthreads();

    // ---- softmax: 4 threads per row, strided keys; emit P as tf32 bits ----
    {
        int part = t & 3;
        int qi = t >> 2;
        float* row = sc + qi * SSTR;
        uint32_t* rowu = scu + qi * SSTR;
        float mx = -1e30f;
#pragma unroll 8
        for (int j = 0; j < 64; j++) mx = fmaxf(mx, row[part + 4 * j]);
        pmax[qi * 4 + part] = mx;
        __syncthreads();
        float rm = fmaxf(fmaxf(pmax[qi * 4], pmax[qi * 4 + 1]),
                         fmaxf(pmax[qi * 4 + 2], pmax[qi * 4 + 3]));
        float s = 0.f;
#pragma unroll 8
        for (int j = 0; j < 64; j++) {
            float e = __expf(row[part + 4 * j] - rm);
            row[part + 4 * j] = e;
            s += e;
        }
        psum[qi * 4 + part] = s;
        __syncthreads();
        float inv = 1.f / (psum[qi * 4] + psum[qi * 4 + 1] +
                           psum[qi * 4 + 2] + psum[qi * 4 + 3]);
#pragma unroll 8
        for (int j = 0; j < 64; j++)
            rowu[part + 4 * j] = f2tf(row[part + 4 * j] * inv);
    }
    __syncthreads();

    // ---- stage 2: O = P V, k-split across warp pairs ----
    {
        int mt2 = w & 3;
        int khalf = w >> 2;
        int m0 = mt2 * 16;
        float4 acc2[4];
#pragma unroll
        for (int nt = 0; nt < 4; nt++) acc2[nt] = make_float4(0.f, 0.f, 0.f, 0.f);

#pragma unroll 4
        for (int ks8 = 0; ks8 < 16; ks8++) {
            int kb = khalf * 128 + ks8 * 8;
            uint32_t af[4];
            af[0] = scu[(m0 + r) * SSTR + kb + c];
            af[1] = scu[(m0 + r + 8) * SSTR + kb + c];
            af[2] = scu[(m0 + r) * SSTR + kb + c + 4];
            af[3] = scu[(m0 + r + 8) * SSTR + kb + c + 4];
#pragma unroll
            for (int nt = 0; nt < 4; nt++) {
                uint32_t bf[2];
                bf[0] = vs[(kb + c) * VSTR + nt * 8 + r];
                bf[1] = vs[(kb + 4 + c) * VSTR + nt * 8 + r];
                mma_tf32(acc2[nt], af, bf);
            }
        }

        int c2 = c * 2;
        if (w >= 4) {
            float* rb = red + mt2 * (16 * RSTR);
#pragma unroll
            for (int nt = 0; nt < 4; nt++) {
                int col = nt * 8 + c2;
                rb[r * RSTR + col]           = acc2[nt].x;
                rb[r * RSTR + col + 1]       = acc2[nt].y;
                rb[(r + 8) * RSTR + col]     = acc2[nt].z;
                rb[(r + 8) * RSTR + col + 1] = acc2[nt].w;
            }
        }
        __syncthreads();
        if (w < 4) {
            const float* rb = red + mt2 * (16 * RSTR);
#pragma unroll
            for (int nt = 0; nt < 4; nt++) {
                int col = nt * 8 + c2;
                float2 o0 = {acc2[nt].x + rb[r * RSTR + col],
                             acc2[nt].y + rb[r * RSTR + col + 1]};
                float2 o1 = {acc2[nt].z + rb[(r + 8) * RSTR + col],
                             acc2[nt].w + rb[(r + 8) * RSTR + col + 1]};
                *(float2*)(g_aout + (size_t)(bp * PIX + m0 + r) * CC
                           + hh * HDH + col) = o0;
                *(float2*)(g_aout + (size_t)(bp * PIX + m0 + r + 8) * CC
                           + hh * HDH + col) = o1;
            }
        }
    }
}

// ---------------------------------------------------------------------------
// Kernel 5: out = (attn_out + lepe) @ Wo + bo via tf32 tensor cores.
// ---------------------------------------------------------------------------
__global__ __launch_bounds__(256) void gemm_out_tc(
    const float* __restrict__ Wo, const float* __restrict__ bo,
    float* __restrict__ out)
{
    __shared__ uint32_t as[2][BK][ASTR];
    __shared__ uint32_t bs[2][BK][ASTR];
    int t = threadIdx.x;
    int warp = t >> 5, lane = t & 31;
    int wm = warp >> 2, wn = warp & 3;
    int m0 = blockIdx.x * 128;
    int n0 = blockIdx.y * 128;

    int arow = t & 127;
    int ka   = (t >> 7) * 8;
    const float* ap;
    const float* lp;
    {
        int m = m0 + arow;
        int b = m / 3136, r2 = m % 3136;
        int p = r2 >> 6, pix = r2 & 63;
        int y  = (p / NW) * WS + (pix >> 3);
        int xx = (p % NW) * WS + (pix & 7);
        lp = g_lepe + (size_t)(b * 3136 + y * WDIM + xx) * CC;
        ap = g_aout + (size_t)m * CC;
    }
    int brow = t >> 4;
    int bq   = (t & 15) * 8;

    float4 acc[4][4];
#pragma unroll
    for (int i = 0; i < 4; i++)
#pragma unroll
        for (int j = 0; j < 4; j++) acc[i][j] = make_float4(0.f, 0.f, 0.f, 0.f);

    {
        float4 a0 = *(const float4*)(ap + ka);
        float4 a1 = *(const float4*)(ap + ka + 4);
        float4 l0 = *(const float4*)(lp + ka);
        float4 l1 = *(const float4*)(lp + ka + 4);
        float4 b0 = *(const float4*)(Wo + (size_t)brow * CC + n0 + bq);
        float4 b1 = *(const float4*)(Wo + (size_t)brow * CC + n0 + bq + 4);
        as[0][ka + 0][arow] = f2tf(a0.x + l0.x); as[0][ka + 1][arow] = f2tf(a0.y + l0.y);
        as[0][ka + 2][arow] = f2tf(a0.z + l0.z); as[0][ka + 3][arow] = f2tf(a0.w + l0.w);
        as[0][ka + 4][arow] = f2tf(a1.x + l1.x); as[0][ka + 5][arow] = f2tf(a1.y + l1.y);
        as[0][ka + 6][arow] = f2tf(a1.z + l1.z); as[0][ka + 7][arow] = f2tf(a1.w + l1.w);
        uint4 u0 = {f2tf(b0.x), f2tf(b0.y), f2tf(b0.z), f2tf(b0.w)};
        uint4 u1 = {f2tf(b1.x), f2tf(b1.y), f2tf(b1.z), f2tf(b1.w)};
        *(uint4*)&bs[0][brow][bq]     = u0;
        *(uint4*)&bs[0][brow][bq + 4] = u1;
    }
    __syncthreads();

    int r = lane >> 2, c = lane & 3;
    int cur = 0;
    for (int k0 = 0; k0 < CC; k0 += BK) {
        bool more = (k0 + BK < CC);
        float4 pa0, pa1, pl0, pl1, pb0, pb1;
        if (more) {
            pa0 = *(const float4*)(ap + k0 + BK + ka);
            pa1 = *(const float4*)(ap + k0 + BK + ka + 4);
            pl0 = *(const float4*)(lp + k0 + BK + ka);
            pl1 = *(const float4*)(lp + k0 + BK + ka + 4);
            pb0 = *(const float4*)(Wo + (size_t)(k0 + BK + brow) * CC + n0 + bq);
            pb1 = *(const float4*)(Wo + (size_t)(k0 + BK + brow) * CC + n0 + bq + 4);
        }
#pragma unroll
        for (int kc = 0; kc < 2; kc++) {
            int kb = kc * 8;
            uint32_t bf[4][2];
#pragma unroll
            for (int nt = 0; nt < 4; nt++) {
                int n = wn * 32 + nt * 8 + r;
                bf[nt][0] = bs[cur][kb + c][n];
                bf[nt][1] = bs[cur][kb + 4 + c][n];
            }
#pragma unroll
            for (int mt = 0; mt < 4; mt++) {
                int m = wm * 64 + mt * 16;
                uint32_t af[4];
                af[0] = as[cur][kb + c][m + r];
                af[1] = as[cur][kb + c][m + r + 8];
                af[2] = as[cur][kb + 4 + c][m + r];
                af[3] = as[cur][kb + 4 + c][m + r + 8];
#pragma unroll
                for (int nt = 0; nt < 4; nt++) mma_tf32(acc[mt][nt], af, bf[nt]);
            }
        }
        if (more) {
            int nxt = cur ^ 1;
            as[nxt][ka + 0][arow] = f2tf(pa0.x + pl0.x); as[nxt][ka + 1][arow] = f2tf(pa0.y + pl0.y);
            as[nxt][ka + 2][arow] = f2tf(pa0.z + pl0.z); as[nxt][ka + 3][arow] = f2tf(pa0.w + pl0.w);
            as[nxt][ka + 4][arow] = f2tf(pa1.x + pl1.x); as[nxt][ka + 5][arow] = f2tf(pa1.y + pl1.y);
            as[nxt][ka + 6][arow] = f2tf(pa1.z + pl1.z); as[nxt][ka + 7][arow] = f2tf(pa1.w + pl1.w);
            uint4 u0 = {f2tf(pb0.x), f2tf(pb0.y), f2tf(pb0.z), f2tf(pb0.w)};
            uint4 u1 = {f2tf(pb1.x), f2tf(pb1.y), f2tf(pb1.z), f2tf(pb1.w)};
            *(uint4*)&bs[nxt][brow][bq]     = u0;
            *(uint4*)&bs[nxt][brow][bq + 4] = u1;
            __syncthreads();
            cur = nxt;
        }
    }

    int c2 = c * 2;
    float2 bb[4];
#pragma unroll
    for (int nt = 0; nt < 4; nt++)
        bb[nt] = *(const float2*)&bo[n0 + wn * 32 + nt * 8 + c2];
#pragma unroll
    for (int mt = 0; mt < 4; mt++) {
#pragma unroll
        for (int h = 0; h < 2; h++) {
            int mm = m0 + wm * 64 + mt * 16 + r + h * 8;
            int bbx = mm / 3136, rr = mm % 3136;
            int pp = rr >> 6, px = rr & 63;
            int yy = (pp / NW) * WS + (px >> 3);
            int xq = (pp % NW) * WS + (px & 7);
            float* orow = out + (size_t)(bbx * 3136 + yy * WDIM + xq) * CC
                        + n0 + wn * 32 + c2;
#pragma unroll
            for (int nt = 0; nt < 4; nt++) {
                float4 a = acc[mt][nt];
                float2 o;
                o.x = (h ? a.z : a.x) + bb[nt].x;
                o.y = (h ? a.w : a.y) + bb[nt].y;
                *(float2*)(orow + nt * 8) = o;
            }
        }
    }
}

// ---------------------------------------------------------------------------
extern "C" void kernel_launch(void* const* d_in, const int* in_sizes, int n_in,
                              void* d_out, int out_size)
{
    const float* x      = (const float*)d_in[0];
    const float* Wqkv   = (const float*)d_in[1];
    const float* bqkv   = (const float*)d_in[2];
    const float* Wo     = (const float*)d_in[3];
    const float* bo     = (const float*)d_in[4];
    const float* lepe_w = (const float*)d_in[5];
    const float* lepe_b = (const float*)d_in[6];
    float* out = (float*)d_out;

    cudaFuncSetAttribute(attn_tc_kernel,
                         cudaFuncAttributeMaxDynamicSharedMemorySize,
                         AT_WORDS * 4);

    // order chosen so the ncu capture slot (position 4) lands on attn
    gemm_qkv_tc<<<dim3(MTOT / 128, QKVW / 128), 256>>>(x, Wqkv, bqkv);
    routing_kernel<<<BB * P2, 256>>>();
    lepe_kernel<<<BB * P2 * 4, 256>>>(lepe_w, lepe_b);
    attn_tc_kernel<<<BB * P2 * NHEAD, 256, AT_WORDS * 4>>>();
    gemm_out_tc<<<dim3(MTOT / 128, CC / 128), 256>>>(Wo, bo, out);
}

// round 15
// speedup vs baseline: 2.8925x; 1.2317x over previous
#include <cuda_runtime.h>
#include <cuda_bf16.h>
#include <cuda_fp16.h>
#include <cstdint>

// Problem constants
#define BB    4
#define HDIM  56
#define WDIM  56
#define CC    256
#define NW    7
#define WS    8
#define P2    49
#define PIX   64
#define NHEAD 8
#define HDH   32
#define TOPK  4
#define MTOT  (BB * P2 * PIX)      // 12544 == BB*HDIM*WDIM
#define QKVW  768
#define SCALE 0.0625f              // 256^-0.5

// Scratch (window-ordered where noted)
__device__ float g_qkv[(size_t)MTOT * QKVW];       // (b,p,pix, 768): q|k|v
__device__ float g_qwin[BB * P2 * CC];
__device__ float g_kwin[BB * P2 * CC];
__device__ int   g_ridx[BB * P2 * TOPK];
__device__ float g_lepe[(size_t)BB * HDIM * WDIM * CC];   // image layout
__device__ float g_aout[(size_t)MTOT * CC];               // window layout

// ---------------------------------------------------------------------------
// mma helpers
// ---------------------------------------------------------------------------
__device__ __forceinline__ uint32_t f2tf(float f) {
    uint32_t u;
    asm("cvt.rna.tf32.f32 %0, %1;" : "=r"(u) : "f"(f));
    return u;
}

__device__ __forceinline__ void mma_tf32(float4& d, const uint32_t a[4],
                                         const uint32_t b[2]) {
    asm volatile(
        "mma.sync.aligned.m16n8k8.row.col.f32.tf32.tf32.f32 "
        "{%0,%1,%2,%3},{%4,%5,%6,%7},{%8,%9},{%0,%1,%2,%3};"
        : "+f"(d.x), "+f"(d.y), "+f"(d.z), "+f"(d.w)
        : "r"(a[0]), "r"(a[1]), "r"(a[2]), "r"(a[3]), "r"(b[0]), "r"(b[1]));
}

__device__ __forceinline__ void mma_f16(float4& d, const uint32_t a[4],
                                        const uint32_t b[2]) {
    asm volatile(
        "mma.sync.aligned.m16n8k16.row.col.f32.f16.f16.f32 "
        "{%0,%1,%2,%3},{%4,%5,%6,%7},{%8,%9},{%0,%1,%2,%3};"
        : "+f"(d.x), "+f"(d.y), "+f"(d.z), "+f"(d.w)
        : "r"(a[0]), "r"(a[1]), "r"(a[2]), "r"(a[3]), "r"(b[0]), "r"(b[1]));
}

__device__ __forceinline__ uint32_t h2pack(float a, float b) {
    __half2 h = __floats2half2_rn(a, b);
    return *(uint32_t*)&h;
}

#define BK    16
#define ASTR  136

// ---------------------------------------------------------------------------
// Kernel 1: QKV GEMM via tf32 tensor cores, with fused per-window q/k means.
// (unchanged from R12)
// ---------------------------------------------------------------------------
__global__ __launch_bounds__(256) void gemm_qkv_tc(
    const float* __restrict__ x, const float* __restrict__ Wqkv,
    const float* __restrict__ bqkv)
{
    __shared__ uint32_t as[2][BK][ASTR];   // [k][m]
    __shared__ uint32_t bs[2][BK][ASTR];   // [k][n]
    int t = threadIdx.x;
    int warp = t >> 5, lane = t & 31;
    int wm = warp >> 2, wn = warp & 3;
    int m0 = blockIdx.x * 128;
    int n0 = blockIdx.y * 128;

    int arow = t & 127;
    int ka   = (t >> 7) * 8;
    {
        int m = m0 + arow;
        int b = m / 3136, r2 = m % 3136;
        int p = r2 >> 6, pix = r2 & 63;
        int y  = (p / NW) * WS + (pix >> 3);
        int xx = (p % NW) * WS + (pix & 7);
        x += (size_t)(b * 3136 + y * WDIM + xx) * CC;
    }
    int brow = t >> 4;
    int bq   = (t & 15) * 8;

    float4 acc[4][4];
#pragma unroll
    for (int i = 0; i < 4; i++)
#pragma unroll
        for (int j = 0; j < 4; j++) acc[i][j] = make_float4(0.f, 0.f, 0.f, 0.f);

    {
        float4 a0 = *(const float4*)(x + ka);
        float4 a1 = *(const float4*)(x + ka + 4);
        float4 b0 = *(const float4*)(Wqkv + (size_t)brow * QKVW + n0 + bq);
        float4 b1 = *(const float4*)(Wqkv + (size_t)brow * QKVW + n0 + bq + 4);
        as[0][ka + 0][arow] = f2tf(a0.x); as[0][ka + 1][arow] = f2tf(a0.y);
        as[0][ka + 2][arow] = f2tf(a0.z); as[0][ka + 3][arow] = f2tf(a0.w);
        as[0][ka + 4][arow] = f2tf(a1.x); as[0][ka + 5][arow] = f2tf(a1.y);
        as[0][ka + 6][arow] = f2tf(a1.z); as[0][ka + 7][arow] = f2tf(a1.w);
        uint4 u0 = {f2tf(b0.x), f2tf(b0.y), f2tf(b0.z), f2tf(b0.w)};
        uint4 u1 = {f2tf(b1.x), f2tf(b1.y), f2tf(b1.z), f2tf(b1.w)};
        *(uint4*)&bs[0][brow][bq]     = u0;
        *(uint4*)&bs[0][brow][bq + 4] = u1;
    }
    __syncthreads();

    int r = lane >> 2, c = lane & 3;
    int cur = 0;
    for (int k0 = 0; k0 < CC; k0 += BK) {
        bool more = (k0 + BK < CC);
        float4 pa0, pa1, pb0, pb1;
        if (more) {
            pa0 = *(const float4*)(x + k0 + BK + ka);
            pa1 = *(const float4*)(x + k0 + BK + ka + 4);
            pb0 = *(const float4*)(Wqkv + (size_t)(k0 + BK + brow) * QKVW + n0 + bq);
            pb1 = *(const float4*)(Wqkv + (size_t)(k0 + BK + brow) * QKVW + n0 + bq + 4);
        }
#pragma unroll
        for (int kc = 0; kc < 2; kc++) {
            int kb = kc * 8;
            uint32_t bf[4][2];
#pragma unroll
            for (int nt = 0; nt < 4; nt++) {
                int n = wn * 32 + nt * 8 + r;
                bf[nt][0] = bs[cur][kb + c][n];
                bf[nt][1] = bs[cur][kb + 4 + c][n];
            }
#pragma unroll
            for (int mt = 0; mt < 4; mt++) {
                int m = wm * 64 + mt * 16;
                uint32_t af[4];
                af[0] = as[cur][kb + c][m + r];
                af[1] = as[cur][kb + c][m + r + 8];
                af[2] = as[cur][kb + 4 + c][m + r];
                af[3] = as[cur][kb + 4 + c][m + r + 8];
#pragma unroll
                for (int nt = 0; nt < 4; nt++) mma_tf32(acc[mt][nt], af, bf[nt]);
            }
        }
        if (more) {
            int nxt = cur ^ 1;
            as[nxt][ka + 0][arow] = f2tf(pa0.x); as[nxt][ka + 1][arow] = f2tf(pa0.y);
            as[nxt][ka + 2][arow] = f2tf(pa0.z); as[nxt][ka + 3][arow] = f2tf(pa0.w);
            as[nxt][ka + 4][arow] = f2tf(pa1.x); as[nxt][ka + 5][arow] = f2tf(pa1.y);
            as[nxt][ka + 6][arow] = f2tf(pa1.z); as[nxt][ka + 7][arow] = f2tf(pa1.w);
            uint4 u0 = {f2tf(pb0.x), f2tf(pb0.y), f2tf(pb0.z), f2tf(pb0.w)};
            uint4 u1 = {f2tf(pb1.x), f2tf(pb1.y), f2tf(pb1.z), f2tf(pb1.w)};
            *(uint4*)&bs[nxt][brow][bq]     = u0;
            *(uint4*)&bs[nxt][brow][bq + 4] = u1;
            __syncthreads();
            cur = nxt;
        }
    }

    int c2 = c * 2;
#pragma unroll
    for (int nt = 0; nt < 4; nt++) {
        int col = n0 + wn * 32 + nt * 8 + c2;
        float2 bb = *(const float2*)&bqkv[col];
#pragma unroll
        for (int mt = 0; mt < 4; mt++) {
            int mm = m0 + wm * 64 + mt * 16 + r;
            float4 a = acc[mt][nt];
            float2 o0 = {a.x + bb.x, a.y + bb.y};
            float2 o1 = {a.z + bb.x, a.w + bb.y};
            *(float2*)(g_qkv + (size_t)mm * QKVW + col) = o0;
            *(float2*)(g_qkv + (size_t)(mm + 8) * QKVW + col) = o1;
        }
    }

    // ---- fused window means (only q|k column blocks: n0 < 512) ----
    if (n0 < 512) {
        int win = 2 * blockIdx.x + wm;
#pragma unroll
        for (int nt = 0; nt < 4; nt++) {
            int col = n0 + wn * 32 + nt * 8 + c2;
            float s0 = 0.f, s1 = 0.f;
#pragma unroll
            for (int mt = 0; mt < 4; mt++) {
                float4 a = acc[mt][nt];
                s0 += a.x + a.z;
                s1 += a.y + a.w;
            }
#pragma unroll
            for (int o = 4; o <= 16; o <<= 1) {
                s0 += __shfl_xor_sync(0xffffffffu, s0, o);
                s1 += __shfl_xor_sync(0xffffffffu, s1, o);
            }
            if (r == 0) {
                float2 bb = *(const float2*)&bqkv[col];
                float m0v = s0 * (1.f / 64.f) + bb.x;
                float m1v = s1 * (1.f / 64.f) + bb.y;
                if (col < CC) {
                    g_qwin[(size_t)win * CC + col] = m0v;
                    g_qwin[(size_t)win * CC + col + 1] = m1v;
                } else {
                    g_kwin[(size_t)win * CC + col - CC] = m0v;
                    g_kwin[(size_t)win * CC + col - CC + 1] = m1v;
                }
            }
        }
    }
}

// ---------------------------------------------------------------------------
// Kernel 2: routing logits + top-4
// ---------------------------------------------------------------------------
__global__ __launch_bounds__(256) void routing_kernel()
{
    __shared__ float lg[P2];
    __shared__ float qsh[CC];
    int b = blockIdx.x / P2;
    int p = blockIdx.x % P2;
    int t = threadIdx.x;
    qsh[t] = g_qwin[(size_t)(b * P2 + p) * CC + t];
    __syncthreads();
    int w = t >> 5, lane = t & 31;
    for (int j = w; j < P2; j += 8) {
        const float* kr = g_kwin + (size_t)(b * P2 + j) * CC;
        float s = 0.f;
#pragma unroll
        for (int cb = 0; cb < CC; cb += 32) s += qsh[cb + lane] * kr[cb + lane];
#pragma unroll
        for (int o = 16; o; o >>= 1) s += __shfl_xor_sync(0xffffffffu, s, o);
        if (lane == 0) lg[j] = s;
    }
    __syncthreads();
    if (t == 0) {
        for (int s = 0; s < TOPK; s++) {
            float best = -1e30f; int bi = 0;
            for (int j = 0; j < P2; j++)
                if (lg[j] > best) { best = lg[j]; bi = j; }
            g_ridx[(b * P2 + p) * TOPK + s] = bi;
            lg[bi] = -1e30f;
        }
    }
}

// ---------------------------------------------------------------------------
// Kernel 3: lepe = depthwise 5x5 conv over v (halo-tile version)
// ---------------------------------------------------------------------------
__global__ __launch_bounds__(256) void lepe_kernel(
    const float* __restrict__ lw, const float* __restrict__ lb)
{
    __shared__ float halo[144 * 64];
    int blk = blockIdx.x;
    int cq = blk & 3;
    int bp = blk >> 2;
    int b = bp / P2, p = bp % P2;
    int y0 = (p / NW) * WS - 2;
    int x0 = (p % NW) * WS - 2;
    int t = threadIdx.x;

#pragma unroll
    for (int i = 0; i < 9; i++) {
        int f = t + i * 256;
        int pix = f >> 4;
        int q4 = (f & 15) * 4;
        int hy = pix / 12, hx = pix % 12;
        int yy = y0 + hy, xs = x0 + hx;
        float4 v = {0.f, 0.f, 0.f, 0.f};
        if (yy >= 0 && yy < HDIM && xs >= 0 && xs < WDIM) {
            int sp = (yy >> 3) * NW + (xs >> 3);
            int spx = ((yy & 7) << 3) + (xs & 7);
            v = *(const float4*)(g_qkv +
                (size_t)((b * P2 + sp) * PIX + spx) * QKVW + 2 * CC + cq * 64 + q4);
        }
        *(float4*)&halo[pix * 64 + q4] = v;
    }

    int c = t & 63;
    int gc = cq * 64 + c;
    float wr[25];
#pragma unroll
    for (int k = 0; k < 25; k++) wr[k] = lw[k * CC + gc];
    float bias = lb[gc];
    __syncthreads();

    int tp = t >> 6;
#pragma unroll
    for (int u = 0; u < 16; u++) {
        int p8 = tp * 16 + u;
        int ly = p8 >> 3, lx = p8 & 7;
        float acc = bias;
#pragma unroll
        for (int dy = 0; dy < 5; dy++)
#pragma unroll
            for (int dx = 0; dx < 5; dx++)
                acc += halo[((ly + dy) * 12 + (lx + dx)) * 64 + c] * wr[dy * 5 + dx];
        g_lepe[((size_t)b * 3136 + (y0 + 2 + ly) * WDIM + (x0 + 2 + lx)) * CC + gc] = acc;
    }
}

// ---------------------------------------------------------------------------
// Kernel 4: attention per (b, window, head) — fp16 tensor cores,
// register-resident softmax, 78.6 KB smem -> 2 CTAs/SM.
//
// smem byte offsets:
//   qs  Q fp16 [64][40]     @ 0       (5120)
//   ksm K fp16 [256][40]    @ 5120    (20480)  [dead after stage 1 -> red]
//   vst V^T fp16 [32][264]  @ 25600   (16896)
//   ps  P fp16 [64][264]    @ 42496   (33792)
//   wred f32 [8][64]        @ 76288   (2048)
//   rstat f32 [64]          @ 78336   (256)    total 78592 B
// ---------------------------------------------------------------------------
#define AH_KS    5120
#define AH_VS    25600
#define AH_PS    42496
#define AH_WRED  76288
#define AH_RSTAT 78336
#define AH_BYTES 78592
#define QH_STR  40
#define KH_STR  40
#define VH_STR  264
#define PH_STR  264
#define RSTR    33

__global__ __launch_bounds__(256, 2) void attn_tc_kernel()
{
    extern __shared__ float sm[];
    __half* qs   = (__half*)sm;
    __half* ksm  = (__half*)((char*)sm + AH_KS);
    __half* vst  = (__half*)((char*)sm + AH_VS);
    __half* ps   = (__half*)((char*)sm + AH_PS);
    float*  wred = (float*)((char*)sm + AH_WRED);
    float*  rstat= (float*)((char*)sm + AH_RSTAT);
    float*  red  = (float*)((char*)sm + AH_KS);   // alias ksm (dead in stage 2)

    int blk = blockIdx.x;
    int b  = blk / (P2 * NHEAD);
    int p  = (blk / NHEAD) % P2;
    int hh = blk % NHEAD;
    int bp = b * P2 + p;
    int t = threadIdx.x;
    int w = t >> 5, lane = t & 31;
    int r = lane >> 2, c = lane & 3;

    int widx[TOPK];
#pragma unroll
    for (int s = 0; s < TOPK; s++) widx[s] = g_ridx[bp * TOPK + s];

    // ---- load Q (scaled) -> fp16 [px][dim] ----
    {
        int px = t & 63;
        int kq = (t >> 6) * 8;
        const float* qb = g_qkv + (size_t)(bp * PIX + px) * QKVW + hh * HDH + kq;
        float4 v0 = *(const float4*)qb;
        float4 v1 = *(const float4*)(qb + 4);
        uint32_t* dst = (uint32_t*)(qs + px * QH_STR + kq);
        dst[0] = h2pack(v0.x * SCALE, v0.y * SCALE);
        dst[1] = h2pack(v0.z * SCALE, v0.w * SCALE);
        dst[2] = h2pack(v1.x * SCALE, v1.y * SCALE);
        dst[3] = h2pack(v1.z * SCALE, v1.w * SCALE);
    }

    // ---- load K -> fp16 [key][dim], key = t ----
    {
        int s = t >> 6, loc = t & 63;
        const float* kb = g_qkv + (size_t)((b * P2 + widx[s]) * PIX + loc) * QKVW
                        + CC + hh * HDH;
        uint32_t* dst = (uint32_t*)(ksm + t * KH_STR);
#pragma unroll
        for (int d4 = 0; d4 < 8; d4++) {
            float4 v = *(const float4*)(kb + d4 * 4);
            dst[d4 * 2]     = h2pack(v.x, v.y);
            dst[d4 * 2 + 1] = h2pack(v.z, v.w);
        }
    }

    // ---- load V transposed -> fp16 [dim][key] ----
    {
        int d4 = (t & 7) * 4;
        int krow = t >> 3;
#pragma unroll
        for (int pass = 0; pass < 8; pass++) {
            int key = pass * 32 + krow;
            int s = key >> 6, loc = key & 63;
            float4 v = *(const float4*)(g_qkv +
                (size_t)((b * P2 + widx[s]) * PIX + loc) * QKVW + 2 * CC
                + hh * HDH + d4);
            vst[(d4 + 0) * VH_STR + key] = __float2half_rn(v.x);
            vst[(d4 + 1) * VH_STR + key] = __float2half_rn(v.y);
            vst[(d4 + 2) * VH_STR + key] = __float2half_rn(v.z);
            vst[(d4 + 3) * VH_STR + key] = __float2half_rn(v.w);
        }
    }
    __syncthreads();

    // ---- stage 1: S = Q K^T  (warp w owns keys w*32..w*32+31) ----
    float4 acc1[4][4];
#pragma unroll
    for (int i = 0; i < 4; i++)
#pragma unroll
        for (int j = 0; j < 4; j++) acc1[i][j] = make_float4(0.f, 0.f, 0.f, 0.f);

#pragma unroll
    for (int ks16 = 0; ks16 < 2; ks16++) {
        int kb = ks16 * 16;
        uint32_t bf[4][2];
#pragma unroll
        for (int nt = 0; nt < 4; nt++) {
            int n = w * 32 + nt * 8 + r;
            bf[nt][0] = *(uint32_t*)&ksm[n * KH_STR + kb + 2 * c];
            bf[nt][1] = *(uint32_t*)&ksm[n * KH_STR + kb + 2 * c + 8];
        }
#pragma unroll
        for (int mt = 0; mt < 4; mt++) {
            int m = mt * 16;
            uint32_t af[4];
            af[0] = *(uint32_t*)&qs[(m + r) * QH_STR + kb + 2 * c];
            af[1] = *(uint32_t*)&qs[(m + r + 8) * QH_STR + kb + 2 * c];
            af[2] = *(uint32_t*)&qs[(m + r) * QH_STR + kb + 2 * c + 8];
            af[3] = *(uint32_t*)&qs[(m + r + 8) * QH_STR + kb + 2 * c + 8];
#pragma unroll
            for (int nt = 0; nt < 4; nt++) mma_f16(acc1[mt][nt], af, bf[nt]);
        }
    }

    // ---- softmax on register-resident S ----
    // thread rows: mt*16+r (x,y) and mt*16+r+8 (z,w); cols w*32+nt*8+2c{,+1}
    {
        float mx0[4], mx1[4];
#pragma unroll
        for (int mt = 0; mt < 4; mt++) {
            float4 a0 = acc1[mt][0], a1 = acc1[mt][1],
                   a2 = acc1[mt][2], a3 = acc1[mt][3];
            mx0[mt] = fmaxf(fmaxf(fmaxf(a0.x, a0.y), fmaxf(a1.x, a1.y)),
                            fmaxf(fmaxf(a2.x, a2.y), fmaxf(a3.x, a3.y)));
            mx1[mt] = fmaxf(fmaxf(fmaxf(a0.z, a0.w), fmaxf(a1.z, a1.w)),
                            fmaxf(fmaxf(a2.z, a2.w), fmaxf(a3.z, a3.w)));
        }
#pragma unroll
        for (int o = 1; o <= 2; o <<= 1)
#pragma unroll
            for (int mt = 0; mt < 4; mt++) {
                mx0[mt] = fmaxf(mx0[mt], __shfl_xor_sync(0xffffffffu, mx0[mt], o));
                mx1[mt] = fmaxf(mx1[mt], __shfl_xor_sync(0xffffffffu, mx1[mt], o));
            }
        if (c == 0) {
#pragma unroll
            for (int mt = 0; mt < 4; mt++) {
                wred[w * 64 + mt * 16 + r]     = mx0[mt];
                wred[w * 64 + mt * 16 + r + 8] = mx1[mt];
            }
        }
        __syncthreads();
        if (t < 64) {
            float m = wred[t];
#pragma unroll
            for (int wi = 1; wi < 8; wi++) m = fmaxf(m, wred[wi * 64 + t]);
            rstat[t] = m;
        }
        __syncthreads();

        float sm0[4], sm1[4];
#pragma unroll
        for (int mt = 0; mt < 4; mt++) {
            float rm0 = rstat[mt * 16 + r];
            float rm1 = rstat[mt * 16 + r + 8];
            float s0 = 0.f, s1 = 0.f;
#pragma unroll
            for (int nt = 0; nt < 4; nt++) {
                float4 a = acc1[mt][nt];
                a.x = __expf(a.x - rm0); a.y = __expf(a.y - rm0);
                a.z = __expf(a.z - rm1); a.w = __expf(a.w - rm1);
                acc1[mt][nt] = a;
                s0 += a.x + a.y;
                s1 += a.z + a.w;
            }
            sm0[mt] = s0; sm1[mt] = s1;
        }
#pragma unroll
        for (int o = 1; o <= 2; o <<= 1)
#pragma unroll
            for (int mt = 0; mt < 4; mt++) {
                sm0[mt] += __shfl_xor_sync(0xffffffffu, sm0[mt], o);
                sm1[mt] += __shfl_xor_sync(0xffffffffu, sm1[mt], o);
            }
        __syncthreads();   // wred max phase fully consumed before overwrite
        if (c == 0) {
#pragma unroll
            for (int mt = 0; mt < 4; mt++) {
                wred[w * 64 + mt * 16 + r]     = sm0[mt];
                wred[w * 64 + mt * 16 + r + 8] = sm1[mt];
            }
        }
        __syncthreads();
        if (t < 64) {
            float s = 0.f;
#pragma unroll
            for (int wi = 0; wi < 8; wi++) s += wred[wi * 64 + t];
            rstat[t] = 1.f / s;
        }
        __syncthreads();

        // normalize + write P fp16
#pragma unroll
        for (int mt = 0; mt < 4; mt++) {
            float i0 = rstat[mt * 16 + r];
            float i1 = rstat[mt * 16 + r + 8];
#pragma unroll
            for (int nt = 0; nt < 4; nt++) {
                int col = w * 32 + nt * 8 + 2 * c;
                float4 a = acc1[mt][nt];
                *(uint32_t*)&ps[(mt * 16 + r) * PH_STR + col] =
                    h2pack(a.x * i0, a.y * i0);
                *(uint32_t*)&ps[(mt * 16 + r + 8) * PH_STR + col] =
                    h2pack(a.z * i1, a.w * i1);
            }
        }
    }
    __syncthreads();

    // ---- stage 2: O = P V, k-split across warp halves ----
    {
        int mt2 = w & 3;
        int khalf = w >> 2;
        int m0 = mt2 * 16;
        float4 acc2[4];
#pragma unroll
        for (int nt = 0; nt < 4; nt++) acc2[nt] = make_float4(0.f, 0.f, 0.f, 0.f);

#pragma unroll
        for (int ks16 = 0; ks16 < 8; ks16++) {
            int kb = khalf * 128 + ks16 * 16;
            uint32_t af[4];
            af[0] = *(uint32_t*)&ps[(m0 + r) * PH_STR + kb + 2 * c];
            af[1] = *(uint32_t*)&ps[(m0 + r + 8) * PH_STR + kb + 2 * c];
            af[2] = *(uint32_t*)&ps[(m0 + r) * PH_STR + kb + 2 * c + 8];
            af[3] = *(uint32_t*)&ps[(m0 + r + 8) * PH_STR + kb + 2 * c + 8];
#pragma unroll
            for (int nt = 0; nt < 4; nt++) {
                uint32_t bf[2];
                bf[0] = *(uint32_t*)&vst[(nt * 8 + r) * VH_STR + kb + 2 * c];
                bf[1] = *(uint32_t*)&vst[(nt * 8 + r) * VH_STR + kb + 2 * c + 8];
                mma_f16(acc2[nt], af, bf);
            }
        }

        int c2 = c * 2;
        if (w >= 4) {
            float* rb = red + mt2 * (16 * RSTR);
#pragma unroll
            for (int nt = 0; nt < 4; nt++) {
                int col = nt * 8 + c2;
                rb[r * RSTR + col]           = acc2[nt].x;
                rb[r * RSTR + col + 1]       = acc2[nt].y;
                rb[(r + 8) * RSTR + col]     = acc2[nt].z;
                rb[(r + 8) * RSTR + col + 1] = acc2[nt].w;
            }
        }
        __syncthreads();
        if (w < 4) {
            const float* rb = red + mt2 * (16 * RSTR);
#pragma unroll
            for (int nt = 0; nt < 4; nt++) {
                int col = nt * 8 + c2;
                float2 o0 = {acc2[nt].x + rb[r * RSTR + col],
                             acc2[nt].y + rb[r * RSTR + col + 1]};
                float2 o1 = {acc2[nt].z + rb[(r + 8) * RSTR + col],
                             acc2[nt].w + rb[(r + 8) * RSTR + col + 1]};
                *(float2*)(g_aout + (size_t)(bp * PIX + m0 + r) * CC
                           + hh * HDH + col) = o0;
                *(float2*)(g_aout + (size_t)(bp * PIX + m0 + r + 8) * CC
                           + hh * HDH + col) = o1;
            }
        }
    }
}

// ---------------------------------------------------------------------------
// Kernel 5: out = (attn_out + lepe) @ Wo + bo via tf32 tensor cores.
// (unchanged from R12)
// ---------------------------------------------------------------------------
__global__ __launch_bounds__(256) void gemm_out_tc(
    const float* __restrict__ Wo, const float* __restrict__ bo,
    float* __restrict__ out)
{
    __shared__ uint32_t as[2][BK][ASTR];
    __shared__ uint32_t bs[2][BK][ASTR];
    int t = threadIdx.x;
    int warp = t >> 5, lane = t & 31;
    int wm = warp >> 2, wn = warp & 3;
    int m0 = blockIdx.x * 128;
    int n0 = blockIdx.y * 128;

    int arow = t & 127;
    int ka   = (t >> 7) * 8;
    const float* ap;
    const float* lp;
    {
        int m = m0 + arow;
        int b = m / 3136, r2 = m % 3136;
        int p = r2 >> 6, pix = r2 & 63;
        int y  = (p / NW) * WS + (pix >> 3);
        int xx = (p % NW) * WS + (pix & 7);
        lp = g_lepe + (size_t)(b * 3136 + y * WDIM + xx) * CC;
        ap = g_aout + (size_t)m * CC;
    }
    int brow = t >> 4;
    int bq   = (t & 15) * 8;

    float4 acc[4][4];
#pragma unroll
    for (int i = 0; i < 4; i++)
#pragma unroll
        for (int j = 0; j < 4; j++) acc[i][j] = make_float4(0.f, 0.f, 0.f, 0.f);

    {
        float4 a0 = *(const float4*)(ap + ka);
        float4 a1 = *(const float4*)(ap + ka + 4);
        float4 l0 = *(const float4*)(lp + ka);
        float4 l1 = *(const float4*)(lp + ka + 4);
        float4 b0 = *(const float4*)(Wo + (size_t)brow * CC + n0 + bq);
        float4 b1 = *(const float4*)(Wo + (size_t)brow * CC + n0 + bq + 4);
        as[0][ka + 0][arow] = f2tf(a0.x + l0.x); as[0][ka + 1][arow] = f2tf(a0.y + l0.y);
        as[0][ka + 2][arow] = f2tf(a0.z + l0.z); as[0][ka + 3][arow] = f2tf(a0.w + l0.w);
        as[0][ka + 4][arow] = f2tf(a1.x + l1.x); as[0][ka + 5][arow] = f2tf(a1.y + l1.y);
        as[0][ka + 6][arow] = f2tf(a1.z + l1.z); as[0][ka + 7][arow] = f2tf(a1.w + l1.w);
        uint4 u0 = {f2tf(b0.x), f2tf(b0.y), f2tf(b0.z), f2tf(b0.w)};
        uint4 u1 = {f2tf(b1.x), f2tf(b1.y), f2tf(b1.z), f2tf(b1.w)};
        *(uint4*)&bs[0][brow][bq]     = u0;
        *(uint4*)&bs[0][brow][bq + 4] = u1;
    }
    __syncthreads();

    int r = lane >> 2, c = lane & 3;
    int cur = 0;
    for (int k0 = 0; k0 < CC; k0 += BK) {
        bool more = (k0 + BK < CC);
        float4 pa0, pa1, pl0, pl1, pb0, pb1;
        if (more) {
            pa0 = *(const float4*)(ap + k0 + BK + ka);
            pa1 = *(const float4*)(ap + k0 + BK + ka + 4);
            pl0 = *(const float4*)(lp + k0 + BK + ka);
            pl1 = *(const float4*)(lp + k0 + BK + ka + 4);
            pb0 = *(const float4*)(Wo + (size_t)(k0 + BK + brow) * CC + n0 + bq);
            pb1 = *(const float4*)(Wo + (size_t)(k0 + BK + brow) * CC + n0 + bq + 4);
        }
#pragma unroll
        for (int kc = 0; kc < 2; kc++) {
            int kb = kc * 8;
            uint32_t bf[4][2];
#pragma unroll
            for (int nt = 0; nt < 4; nt++) {
                int n = wn * 32 + nt * 8 + r;
                bf[nt][0] = bs[cur][kb + c][n];
                bf[nt][1] = bs[cur][kb + 4 + c][n];
            }
#pragma unroll
            for (int mt = 0; mt < 4; mt++) {
                int m = wm * 64 + mt * 16;
                uint32_t af[4];
                af[0] = as[cur][kb + c][m + r];
                af[1] = as[cur][kb + c][m + r + 8];
                af[2] = as[cur][kb + 4 + c][m + r];
                af[3] = as[cur][kb + 4 + c][m + r + 8];
#pragma unroll
                for (int nt = 0; nt < 4; nt++) mma_tf32(acc[mt][nt], af, bf[nt]);
            }
        }
        if (more) {
            int nxt = cur ^ 1;
            as[nxt][ka + 0][arow] = f2tf(pa0.x + pl0.x); as[nxt][ka + 1][arow] = f2tf(pa0.y + pl0.y);
            as[nxt][ka + 2][arow] = f2tf(pa0.z + pl0.z); as[nxt][ka + 3][arow] = f2tf(pa0.w + pl0.w);
            as[nxt][ka + 4][arow] = f2tf(pa1.x + pl1.x); as[nxt][ka + 5][arow] = f2tf(pa1.y + pl1.y);
            as[nxt][ka + 6][arow] = f2tf(pa1.z + pl1.z); as[nxt][ka + 7][arow] = f2tf(pa1.w + pl1.w);
            uint4 u0 = {f2tf(pb0.x), f2tf(pb0.y), f2tf(pb0.z), f2tf(pb0.w)};
            uint4 u1 = {f2tf(pb1.x), f2tf(pb1.y), f2tf(pb1.z), f2tf(pb1.w)};
            *(uint4*)&bs[nxt][brow][bq]     = u0;
            *(uint4*)&bs[nxt][brow][bq + 4] = u1;
            __syncthreads();
            cur = nxt;
        }
    }

    int c2 = c * 2;
    float2 bb[4];
#pragma unroll
    for (int nt = 0; nt < 4; nt++)
        bb[nt] = *(const float2*)&bo[n0 + wn * 32 + nt * 8 + c2];
#pragma unroll
    for (int mt = 0; mt < 4; mt++) {
#pragma unroll
        for (int h = 0; h < 2; h++) {
            int mm = m0 + wm * 64 + mt * 16 + r + h * 8;
            int bbx = mm / 3136, rr = mm % 3136;
            int pp = rr >> 6, px = rr & 63;
            int yy = (pp / NW) * WS + (px >> 3);
            int xq = (pp % NW) * WS + (px & 7);
            float* orow = out + (size_t)(bbx * 3136 + yy * WDIM + xq) * CC
                        + n0 + wn * 32 + c2;
#pragma unroll
            for (int nt = 0; nt < 4; nt++) {
                float4 a = acc[mt][nt];
                float2 o;
                o.x = (h ? a.z : a.x) + bb[nt].x;
                o.y = (h ? a.w : a.y) + bb[nt].y;
                *(float2*)(orow + nt * 8) = o;
            }
        }
    }
}

// ---------------------------------------------------------------------------
extern "C" void kernel_launch(void* const* d_in, const int* in_sizes, int n_in,
                              void* d_out, int out_size)
{
    const float* x      = (const float*)d_in[0];
    const float* Wqkv   = (const float*)d_in[1];
    const float* bqkv   = (const float*)d_in[2];
    const float* Wo     = (const float*)d_in[3];
    const float* bo     = (const float*)d_in[4];
    const float* lepe_w = (const float*)d_in[5];
    const float* lepe_b = (const float*)d_in[6];
    float* out = (float*)d_out;

    cudaFuncSetAttribute(attn_tc_kernel,
                         cudaFuncAttributeMaxDynamicSharedMemorySize,
                         AH_BYTES);

    // order keeps attn in the ncu capture slot (4th launch)
    gemm_qkv_tc<<<dim3(MTOT / 128, QKVW / 128), 256>>>(x, Wqkv, bqkv);
    routing_kernel<<<BB * P2, 256>>>();
    lepe_kernel<<<BB * P2 * 4, 256>>>(lepe_w, lepe_b);
    attn_tc_kernel<<<BB * P2 * NHEAD, 256, AH_BYTES>>>();
    gemm_out_tc<<<dim3(MTOT / 128, CC / 128), 256>>>(Wo, bo, out);
}

// round 17
// speedup vs baseline: 3.7269x; 1.2885x over previous
#include <cuda_runtime.h>
#include <cuda_bf16.h>
#include <cuda_fp16.h>
#include <cstdint>

// Problem constants
#define BB    4
#define HDIM  56
#define WDIM  56
#define CC    256
#define NW    7
#define WS    8
#define P2    49
#define PIX   64
#define NHEAD 8
#define HDH   32
#define TOPK  4
#define MTOT  (BB * P2 * PIX)      // 12544 == BB*HDIM*WDIM
#define QKVW  768
#define SCALE 0.0625f              // 256^-0.5

// Scratch (window-ordered where noted)
__device__ float g_qkv[(size_t)MTOT * QKVW];       // (b,p,pix, 768): q|k|v
__device__ float g_qwin[BB * P2 * CC];
__device__ float g_kwin[BB * P2 * CC];
__device__ int   g_ridx[BB * P2 * TOPK];
__device__ float g_lepe[(size_t)BB * HDIM * WDIM * CC];   // image layout
__device__ float g_aout[(size_t)MTOT * CC];               // window layout

// ---------------------------------------------------------------------------
// mma helpers
// ---------------------------------------------------------------------------
__device__ __forceinline__ void mma_f16(float4& d, const uint32_t a[4],
                                        const uint32_t b[2]) {
    asm volatile(
        "mma.sync.aligned.m16n8k16.row.col.f32.f16.f16.f32 "
        "{%0,%1,%2,%3},{%4,%5,%6,%7},{%8,%9},{%0,%1,%2,%3};"
        : "+f"(d.x), "+f"(d.y), "+f"(d.z), "+f"(d.w)
        : "r"(a[0]), "r"(a[1]), "r"(a[2]), "r"(a[3]), "r"(b[0]), "r"(b[1]));
}

__device__ __forceinline__ uint32_t h2pack(float a, float b) {
    __half2 h = __floats2half2_rn(a, b);
    return *(uint32_t*)&h;
}

// ---------------------------------------------------------------------------
// Kernel 1: QKV GEMM via fp16 tensor cores (m16n8k16), fused window means.
// 128x128 block, BK=32, double-buffered, 8 warps (2x4), warp tile 64x32.
// smem: A [m][k] and B [n][k], stride 40 halves -> conflict-free fragments.
// ---------------------------------------------------------------------------
__global__ __launch_bounds__(256, 2) void gemm_qkv_f16(
    const float* __restrict__ x, const float* __restrict__ Wqkv,
    const float* __restrict__ bqkv)
{
    __shared__ __half a_s[2][128][40];
    __shared__ __half b_s[2][128][40];
    int t = threadIdx.x;
    int warp = t >> 5, lane = t & 31;
    int wm = warp >> 2, wn = warp & 3;
    int m0 = blockIdx.x * 128, n0 = blockIdx.y * 128;
    int r = lane >> 2, c = lane & 3;

    // A loader: (row, 16-k half) = (t>>1, t&1)
    int arow = t >> 1, akh = (t & 1) * 16;
    const float* ap;
    {
        int m = m0 + arow;
        int b = m / 3136, r2 = m % 3136;
        int p = r2 >> 6, pix = r2 & 63;
        int y  = (p / NW) * WS + (pix >> 3);
        int xx = (p % NW) * WS + (pix & 7);
        ap = x + (size_t)(b * 3136 + y * WDIM + xx) * CC + akh;
    }
    // B loader: (n, 16-k half) = (t>>1, t&1); W is [k][n] row-major
    int bn = t >> 1, bkq = (t & 1) * 16;
    const float* bp = Wqkv + n0 + bn;

    float4 acc[4][4];
#pragma unroll
    for (int i = 0; i < 4; i++)
#pragma unroll
        for (int j = 0; j < 4; j++) acc[i][j] = make_float4(0.f, 0.f, 0.f, 0.f);

    uint32_t pa[8], pb[8];
    // prime buffer 0
    {
        const float4* a4 = (const float4*)ap;
        float4 v0 = a4[0], v1 = a4[1], v2 = a4[2], v3 = a4[3];
        pa[0] = h2pack(v0.x, v0.y); pa[1] = h2pack(v0.z, v0.w);
        pa[2] = h2pack(v1.x, v1.y); pa[3] = h2pack(v1.z, v1.w);
        pa[4] = h2pack(v2.x, v2.y); pa[5] = h2pack(v2.z, v2.w);
        pa[6] = h2pack(v3.x, v3.y); pa[7] = h2pack(v3.z, v3.w);
#pragma unroll
        for (int j = 0; j < 8; j++)
            pb[j] = h2pack(bp[(bkq + 2 * j) * QKVW], bp[(bkq + 2 * j + 1) * QKVW]);
        uint32_t* ad = (uint32_t*)&a_s[0][arow][akh];
        uint32_t* bd = (uint32_t*)&b_s[0][bn][bkq];
#pragma unroll
        for (int j = 0; j < 8; j++) { ad[j] = pa[j]; bd[j] = pb[j]; }
    }
    __syncthreads();

    int cur = 0;
    for (int k0 = 0; k0 < CC; k0 += 32) {
        bool more = (k0 + 32 < CC);
        if (more) {
            const float4* a4 = (const float4*)(ap + k0 + 32);
            float4 v0 = a4[0], v1 = a4[1], v2 = a4[2], v3 = a4[3];
            pa[0] = h2pack(v0.x, v0.y); pa[1] = h2pack(v0.z, v0.w);
            pa[2] = h2pack(v1.x, v1.y); pa[3] = h2pack(v1.z, v1.w);
            pa[4] = h2pack(v2.x, v2.y); pa[5] = h2pack(v2.z, v2.w);
            pa[6] = h2pack(v3.x, v3.y); pa[7] = h2pack(v3.z, v3.w);
#pragma unroll
            for (int j = 0; j < 8; j++)
                pb[j] = h2pack(bp[(k0 + 32 + bkq + 2 * j) * QKVW],
                               bp[(k0 + 32 + bkq + 2 * j + 1) * QKVW]);
        }
#pragma unroll
        for (int kc = 0; kc < 2; kc++) {
            int kb = kc * 16;
            uint32_t bf[4][2];
#pragma unroll
            for (int nt = 0; nt < 4; nt++) {
                int n = wn * 32 + nt * 8 + r;
                bf[nt][0] = *(uint32_t*)&b_s[cur][n][kb + 2 * c];
                bf[nt][1] = *(uint32_t*)&b_s[cur][n][kb + 2 * c + 8];
            }
#pragma unroll
            for (int mt = 0; mt < 4; mt++) {
                int m = wm * 64 + mt * 16;
                uint32_t af[4];
                af[0] = *(uint32_t*)&a_s[cur][m + r][kb + 2 * c];
                af[1] = *(uint32_t*)&a_s[cur][m + r + 8][kb + 2 * c];
                af[2] = *(uint32_t*)&a_s[cur][m + r][kb + 2 * c + 8];
                af[3] = *(uint32_t*)&a_s[cur][m + r + 8][kb + 2 * c + 8];
#pragma unroll
                for (int nt = 0; nt < 4; nt++) mma_f16(acc[mt][nt], af, bf[nt]);
            }
        }
        if (more) {
            int nxt = cur ^ 1;
            uint32_t* ad = (uint32_t*)&a_s[nxt][arow][akh];
            uint32_t* bd = (uint32_t*)&b_s[nxt][bn][bkq];
#pragma unroll
            for (int j = 0; j < 8; j++) { ad[j] = pa[j]; bd[j] = pb[j]; }
            __syncthreads();
            cur = nxt;
        }
    }

    int c2 = c * 2;
#pragma unroll
    for (int nt = 0; nt < 4; nt++) {
        int col = n0 + wn * 32 + nt * 8 + c2;
        float2 bb = *(const float2*)&bqkv[col];
#pragma unroll
        for (int mt = 0; mt < 4; mt++) {
            int mm = m0 + wm * 64 + mt * 16 + r;
            float4 a = acc[mt][nt];
            float2 o0 = {a.x + bb.x, a.y + bb.y};
            float2 o1 = {a.z + bb.x, a.w + bb.y};
            *(float2*)(g_qkv + (size_t)mm * QKVW + col) = o0;
            *(float2*)(g_qkv + (size_t)(mm + 8) * QKVW + col) = o1;
        }
    }

    // ---- fused window means (only q|k column blocks: n0 < 512) ----
    if (n0 < 512) {
        int win = 2 * blockIdx.x + wm;
#pragma unroll
        for (int nt = 0; nt < 4; nt++) {
            int col = n0 + wn * 32 + nt * 8 + c2;
            float s0 = 0.f, s1 = 0.f;
#pragma unroll
            for (int mt = 0; mt < 4; mt++) {
                float4 a = acc[mt][nt];
                s0 += a.x + a.z;
                s1 += a.y + a.w;
            }
#pragma unroll
            for (int o = 4; o <= 16; o <<= 1) {
                s0 += __shfl_xor_sync(0xffffffffu, s0, o);
                s1 += __shfl_xor_sync(0xffffffffu, s1, o);
            }
            if (r == 0) {
                float2 bb = *(const float2*)&bqkv[col];
                float m0v = s0 * (1.f / 64.f) + bb.x;
                float m1v = s1 * (1.f / 64.f) + bb.y;
                if (col < CC) {
                    g_qwin[(size_t)win * CC + col] = m0v;
                    g_qwin[(size_t)win * CC + col + 1] = m1v;
                } else {
                    g_kwin[(size_t)win * CC + col - CC] = m0v;
                    g_kwin[(size_t)win * CC + col - CC + 1] = m1v;
                }
            }
        }
    }
}

// ---------------------------------------------------------------------------
// Kernel 2: routing logits + top-4
// ---------------------------------------------------------------------------
__global__ __launch_bounds__(256) void routing_kernel()
{
    __shared__ float lg[P2];
    __shared__ float qsh[CC];
    int b = blockIdx.x / P2;
    int p = blockIdx.x % P2;
    int t = threadIdx.x;
    qsh[t] = g_qwin[(size_t)(b * P2 + p) * CC + t];
    __syncthreads();
    int w = t >> 5, lane = t & 31;
    for (int j = w; j < P2; j += 8) {
        const float* kr = g_kwin + (size_t)(b * P2 + j) * CC;
        float s = 0.f;
#pragma unroll
        for (int cb = 0; cb < CC; cb += 32) s += qsh[cb + lane] * kr[cb + lane];
#pragma unroll
        for (int o = 16; o; o >>= 1) s += __shfl_xor_sync(0xffffffffu, s, o);
        if (lane == 0) lg[j] = s;
    }
    __syncthreads();
    if (t == 0) {
        for (int s = 0; s < TOPK; s++) {
            float best = -1e30f; int bi = 0;
            for (int j = 0; j < P2; j++)
                if (lg[j] > best) { best = lg[j]; bi = j; }
            g_ridx[(b * P2 + p) * TOPK + s] = bi;
            lg[bi] = -1e30f;
        }
    }
}

// ---------------------------------------------------------------------------
// Kernel 3: lepe = depthwise 5x5 conv over v (halo-tile version)
// ---------------------------------------------------------------------------
__global__ __launch_bounds__(256) void lepe_kernel(
    const float* __restrict__ lw, const float* __restrict__ lb)
{
    __shared__ float halo[144 * 64];
    int blk = blockIdx.x;
    int cq = blk & 3;
    int bp = blk >> 2;
    int b = bp / P2, p = bp % P2;
    int y0 = (p / NW) * WS - 2;
    int x0 = (p % NW) * WS - 2;
    int t = threadIdx.x;

#pragma unroll
    for (int i = 0; i < 9; i++) {
        int f = t + i * 256;
        int pix = f >> 4;
        int q4 = (f & 15) * 4;
        int hy = pix / 12, hx = pix % 12;
        int yy = y0 + hy, xs = x0 + hx;
        float4 v = {0.f, 0.f, 0.f, 0.f};
        if (yy >= 0 && yy < HDIM && xs >= 0 && xs < WDIM) {
            int sp = (yy >> 3) * NW + (xs >> 3);
            int spx = ((yy & 7) << 3) + (xs & 7);
            v = *(const float4*)(g_qkv +
                (size_t)((b * P2 + sp) * PIX + spx) * QKVW + 2 * CC + cq * 64 + q4);
        }
        *(float4*)&halo[pix * 64 + q4] = v;
    }

    int c = t & 63;
    int gc = cq * 64 + c;
    float wr[25];
#pragma unroll
    for (int k = 0; k < 25; k++) wr[k] = lw[k * CC + gc];
    float bias = lb[gc];
    __syncthreads();

    int tp = t >> 6;
#pragma unroll
    for (int u = 0; u < 16; u++) {
        int p8 = tp * 16 + u;
        int ly = p8 >> 3, lx = p8 & 7;
        float acc = bias;
#pragma unroll
        for (int dy = 0; dy < 5; dy++)
#pragma unroll
            for (int dx = 0; dx < 5; dx++)
                acc += halo[((ly + dy) * 12 + (lx + dx)) * 64 + c] * wr[dy * 5 + dx];
        g_lepe[((size_t)b * 3136 + (y0 + 2 + ly) * WDIM + (x0 + 2 + lx)) * CC + gc] = acc;
    }
}

// ---------------------------------------------------------------------------
// Kernel 4: attention per (b, window, head) — fp16 tensor cores,
// register-resident softmax, 78.6 KB smem -> 2 CTAs/SM. (unchanged R15)
// ---------------------------------------------------------------------------
#define AH_KS    5120
#define AH_VS    25600
#define AH_PS    42496
#define AH_WRED  76288
#define AH_RSTAT 78336
#define AH_BYTES 78592
#define QH_STR  40
#define KH_STR  40
#define VH_STR  264
#define PH_STR  264
#define RSTR    33

__global__ __launch_bounds__(256, 2) void attn_tc_kernel()
{
    extern __shared__ float sm[];
    __half* qs   = (__half*)sm;
    __half* ksm  = (__half*)((char*)sm + AH_KS);
    __half* vst  = (__half*)((char*)sm + AH_VS);
    __half* ps   = (__half*)((char*)sm + AH_PS);
    float*  wred = (float*)((char*)sm + AH_WRED);
    float*  rstat= (float*)((char*)sm + AH_RSTAT);
    float*  red  = (float*)((char*)sm + AH_KS);   // alias ksm (dead in stage 2)

    int blk = blockIdx.x;
    int b  = blk / (P2 * NHEAD);
    int p  = (blk / NHEAD) % P2;
    int hh = blk % NHEAD;
    int bp = b * P2 + p;
    int t = threadIdx.x;
    int w = t >> 5, lane = t & 31;
    int r = lane >> 2, c = lane & 3;

    int widx[TOPK];
#pragma unroll
    for (int s = 0; s < TOPK; s++) widx[s] = g_ridx[bp * TOPK + s];

    // ---- load Q (scaled) -> fp16 [px][dim] ----
    {
        int px = t & 63;
        int kq = (t >> 6) * 8;
        const float* qb = g_qkv + (size_t)(bp * PIX + px) * QKVW + hh * HDH + kq;
        float4 v0 = *(const float4*)qb;
        float4 v1 = *(const float4*)(qb + 4);
        uint32_t* dst = (uint32_t*)(qs + px * QH_STR + kq);
        dst[0] = h2pack(v0.x * SCALE, v0.y * SCALE);
        dst[1] = h2pack(v0.z * SCALE, v0.w * SCALE);
        dst[2] = h2pack(v1.x * SCALE, v1.y * SCALE);
        dst[3] = h2pack(v1.z * SCALE, v1.w * SCALE);
    }

    // ---- load K -> fp16 [key][dim], key = t ----
    {
        int s = t >> 6, loc = t & 63;
        const float* kb = g_qkv + (size_t)((b * P2 + widx[s]) * PIX + loc) * QKVW
                        + CC + hh * HDH;
        uint32_t* dst = (uint32_t*)(ksm + t * KH_STR);
#pragma unroll
        for (int d4 = 0; d4 < 8; d4++) {
            float4 v = *(const float4*)(kb + d4 * 4);
            dst[d4 * 2]     = h2pack(v.x, v.y);
            dst[d4 * 2 + 1] = h2pack(v.z, v.w);
        }
    }

    // ---- load V transposed -> fp16 [dim][key] ----
    {
        int d4 = (t & 7) * 4;
        int krow = t >> 3;
#pragma unroll
        for (int pass = 0; pass < 8; pass++) {
            int key = pass * 32 + krow;
            int s = key >> 6, loc = key & 63;
            float4 v = *(const float4*)(g_qkv +
                (size_t)((b * P2 + widx[s]) * PIX + loc) * QKVW + 2 * CC
                + hh * HDH + d4);
            vst[(d4 + 0) * VH_STR + key] = __float2half_rn(v.x);
            vst[(d4 + 1) * VH_STR + key] = __float2half_rn(v.y);
            vst[(d4 + 2) * VH_STR + key] = __float2half_rn(v.z);
            vst[(d4 + 3) * VH_STR + key] = __float2half_rn(v.w);
        }
    }
    __syncthreads();

    // ---- stage 1: S = Q K^T  (warp w owns keys w*32..w*32+31) ----
    float4 acc1[4][4];
#pragma unroll
    for (int i = 0; i < 4; i++)
#pragma unroll
        for (int j = 0; j < 4; j++) acc1[i][j] = make_float4(0.f, 0.f, 0.f, 0.f);

#pragma unroll
    for (int ks16 = 0; ks16 < 2; ks16++) {
        int kb = ks16 * 16;
        uint32_t bf[4][2];
#pragma unroll
        for (int nt = 0; nt < 4; nt++) {
            int n = w * 32 + nt * 8 + r;
            bf[nt][0] = *(uint32_t*)&ksm[n * KH_STR + kb + 2 * c];
            bf[nt][1] = *(uint32_t*)&ksm[n * KH_STR + kb + 2 * c + 8];
        }
#pragma unroll
        for (int mt = 0; mt < 4; mt++) {
            int m = mt * 16;
            uint32_t af[4];
            af[0] = *(uint32_t*)&qs[(m + r) * QH_STR + kb + 2 * c];
            af[1] = *(uint32_t*)&qs[(m + r + 8) * QH_STR + kb + 2 * c];
            af[2] = *(uint32_t*)&qs[(m + r) * QH_STR + kb + 2 * c + 8];
            af[3] = *(uint32_t*)&qs[(m + r + 8) * QH_STR + kb + 2 * c + 8];
#pragma unroll
            for (int nt = 0; nt < 4; nt++) mma_f16(acc1[mt][nt], af, bf[nt]);
        }
    }

    // ---- softmax on register-resident S ----
    {
        float mx0[4], mx1[4];
#pragma unroll
        for (int mt = 0; mt < 4; mt++) {
            float4 a0 = acc1[mt][0], a1 = acc1[mt][1],
                   a2 = acc1[mt][2], a3 = acc1[mt][3];
            mx0[mt] = fmaxf(fmaxf(fmaxf(a0.x, a0.y), fmaxf(a1.x, a1.y)),
                            fmaxf(fmaxf(a2.x, a2.y), fmaxf(a3.x, a3.y)));
            mx1[mt] = fmaxf(fmaxf(fmaxf(a0.z, a0.w), fmaxf(a1.z, a1.w)),
                            fmaxf(fmaxf(a2.z, a2.w), fmaxf(a3.z, a3.w)));
        }
#pragma unroll
        for (int o = 1; o <= 2; o <<= 1)
#pragma unroll
            for (int mt = 0; mt < 4; mt++) {
                mx0[mt] = fmaxf(mx0[mt], __shfl_xor_sync(0xffffffffu, mx0[mt], o));
                mx1[mt] = fmaxf(mx1[mt], __shfl_xor_sync(0xffffffffu, mx1[mt], o));
            }
        if (c == 0) {
#pragma unroll
            for (int mt = 0; mt < 4; mt++) {
                wred[w * 64 + mt * 16 + r]     = mx0[mt];
                wred[w * 64 + mt * 16 + r + 8] = mx1[mt];
            }
        }
        __syncthreads();
        if (t < 64) {
            float m = wred[t];
#pragma unroll
            for (int wi = 1; wi < 8; wi++) m = fmaxf(m, wred[wi * 64 + t]);
            rstat[t] = m;
        }
        __syncthreads();

        float sm0[4], sm1[4];
#pragma unroll
        for (int mt = 0; mt < 4; mt++) {
            float rm0 = rstat[mt * 16 + r];
            float rm1 = rstat[mt * 16 + r + 8];
            float s0 = 0.f, s1 = 0.f;
#pragma unroll
            for (int nt = 0; nt < 4; nt++) {
                float4 a = acc1[mt][nt];
                a.x = __expf(a.x - rm0); a.y = __expf(a.y - rm0);
                a.z = __expf(a.z - rm1); a.w = __expf(a.w - rm1);
                acc1[mt][nt] = a;
                s0 += a.x + a.y;
                s1 += a.z + a.w;
            }
            sm0[mt] = s0; sm1[mt] = s1;
        }
#pragma unroll
        for (int o = 1; o <= 2; o <<= 1)
#pragma unroll
            for (int mt = 0; mt < 4; mt++) {
                sm0[mt] += __shfl_xor_sync(0xffffffffu, sm0[mt], o);
                sm1[mt] += __shfl_xor_sync(0xffffffffu, sm1[mt], o);
            }
        __syncthreads();
        if (c == 0) {
#pragma unroll
            for (int mt = 0; mt < 4; mt++) {
                wred[w * 64 + mt * 16 + r]     = sm0[mt];
                wred[w * 64 + mt * 16 + r + 8] = sm1[mt];
            }
        }
        __syncthreads();
        if (t < 64) {
            float s = 0.f;
#pragma unroll
            for (int wi = 0; wi < 8; wi++) s += wred[wi * 64 + t];
            rstat[t] = 1.f / s;
        }
        __syncthreads();

#pragma unroll
        for (int mt = 0; mt < 4; mt++) {
            float i0 = rstat[mt * 16 + r];
            float i1 = rstat[mt * 16 + r + 8];
#pragma unroll
            for (int nt = 0; nt < 4; nt++) {
                int col = w * 32 + nt * 8 + 2 * c;
                float4 a = acc1[mt][nt];
                *(uint32_t*)&ps[(mt * 16 + r) * PH_STR + col] =
                    h2pack(a.x * i0, a.y * i0);
                *(uint32_t*)&ps[(mt * 16 + r + 8) * PH_STR + col] =
                    h2pack(a.z * i1, a.w * i1);
            }
        }
    }
    __syncthreads();

    // ---- stage 2: O = P V, k-split across warp halves ----
    {
        int mt2 = w & 3;
        int khalf = w >> 2;
        int m0 = mt2 * 16;
        float4 acc2[4];
#pragma unroll
        for (int nt = 0; nt < 4; nt++) acc2[nt] = make_float4(0.f, 0.f, 0.f, 0.f);

#pragma unroll
        for (int ks16 = 0; ks16 < 8; ks16++) {
            int kb = khalf * 128 + ks16 * 16;
            uint32_t af[4];
            af[0] = *(uint32_t*)&ps[(m0 + r) * PH_STR + kb + 2 * c];
            af[1] = *(uint32_t*)&ps[(m0 + r + 8) * PH_STR + kb + 2 * c];
            af[2] = *(uint32_t*)&ps[(m0 + r) * PH_STR + kb + 2 * c + 8];
            af[3] = *(uint32_t*)&ps[(m0 + r + 8) * PH_STR + kb + 2 * c + 8];
#pragma unroll
            for (int nt = 0; nt < 4; nt++) {
                uint32_t bf[2];
                bf[0] = *(uint32_t*)&vst[(nt * 8 + r) * VH_STR + kb + 2 * c];
                bf[1] = *(uint32_t*)&vst[(nt * 8 + r) * VH_STR + kb + 2 * c + 8];
                mma_f16(acc2[nt], af, bf);
            }
        }

        int c2 = c * 2;
        if (w >= 4) {
            float* rb = red + mt2 * (16 * RSTR);
#pragma unroll
            for (int nt = 0; nt < 4; nt++) {
                int col = nt * 8 + c2;
                rb[r * RSTR + col]           = acc2[nt].x;
                rb[r * RSTR + col + 1]       = acc2[nt].y;
                rb[(r + 8) * RSTR + col]     = acc2[nt].z;
                rb[(r + 8) * RSTR + col + 1] = acc2[nt].w;
            }
        }
        __syncthreads();
        if (w < 4) {
            const float* rb = red + mt2 * (16 * RSTR);
#pragma unroll
            for (int nt = 0; nt < 4; nt++) {
                int col = nt * 8 + c2;
                float2 o0 = {acc2[nt].x + rb[r * RSTR + col],
                             acc2[nt].y + rb[r * RSTR + col + 1]};
                float2 o1 = {acc2[nt].z + rb[(r + 8) * RSTR + col],
                             acc2[nt].w + rb[(r + 8) * RSTR + col + 1]};
                *(float2*)(g_aout + (size_t)(bp * PIX + m0 + r) * CC
                           + hh * HDH + col) = o0;
                *(float2*)(g_aout + (size_t)(bp * PIX + m0 + r + 8) * CC
                           + hh * HDH + col) = o1;
            }
        }
    }
}

// ---------------------------------------------------------------------------
// Kernel 5: out = (attn_out + lepe) @ Wo + bo via fp16 tensor cores,
// image-layout output.
// ---------------------------------------------------------------------------
__global__ __launch_bounds__(256, 2) void gemm_out_f16(
    const float* __restrict__ Wo, const float* __restrict__ bo,
    float* __restrict__ out)
{
    __shared__ __half a_s[2][128][40];
    __shared__ __half b_s[2][128][40];
    int t = threadIdx.x;
    int warp = t >> 5, lane = t & 31;
    int wm = warp >> 2, wn = warp & 3;
    int m0 = blockIdx.x * 128, n0 = blockIdx.y * 128;
    int r = lane >> 2, c = lane & 3;

    int arow = t >> 1, akh = (t & 1) * 16;
    const float* ap;
    const float* lp;
    {
        int m = m0 + arow;
        int b = m / 3136, r2 = m % 3136;
        int p = r2 >> 6, pix = r2 & 63;
        int y  = (p / NW) * WS + (pix >> 3);
        int xx = (p % NW) * WS + (pix & 7);
        lp = g_lepe + (size_t)(b * 3136 + y * WDIM + xx) * CC + akh;
        ap = g_aout + (size_t)m * CC + akh;
    }
    int bn = t >> 1, bkq = (t & 1) * 16;
    const float* bp = Wo + n0 + bn;

    float4 acc[4][4];
#pragma unroll
    for (int i = 0; i < 4; i++)
#pragma unroll
        for (int j = 0; j < 4; j++) acc[i][j] = make_float4(0.f, 0.f, 0.f, 0.f);

    uint32_t pa[8], pb[8];
    {
        const float4* a4 = (const float4*)ap;
        const float4* l4 = (const float4*)lp;
#pragma unroll
        for (int q = 0; q < 4; q++) {
            float4 v = a4[q], l = l4[q];
            pa[q * 2]     = h2pack(v.x + l.x, v.y + l.y);
            pa[q * 2 + 1] = h2pack(v.z + l.z, v.w + l.w);
        }
#pragma unroll
        for (int j = 0; j < 8; j++)
            pb[j] = h2pack(bp[(bkq + 2 * j) * CC], bp[(bkq + 2 * j + 1) * CC]);
        uint32_t* ad = (uint32_t*)&a_s[0][arow][akh];
        uint32_t* bd = (uint32_t*)&b_s[0][bn][bkq];
#pragma unroll
        for (int j = 0; j < 8; j++) { ad[j] = pa[j]; bd[j] = pb[j]; }
    }
    __syncthreads();

    int cur = 0;
    for (int k0 = 0; k0 < CC; k0 += 32) {
        bool more = (k0 + 32 < CC);
        if (more) {
            const float4* a4 = (const float4*)(ap + k0 + 32);
            const float4* l4 = (const float4*)(lp + k0 + 32);
#pragma unroll
            for (int q = 0; q < 4; q++) {
                float4 v = a4[q], l = l4[q];
                pa[q * 2]     = h2pack(v.x + l.x, v.y + l.y);
                pa[q * 2 + 1] = h2pack(v.z + l.z, v.w + l.w);
            }
#pragma unroll
            for (int j = 0; j < 8; j++)
                pb[j] = h2pack(bp[(k0 + 32 + bkq + 2 * j) * CC],
                               bp[(k0 + 32 + bkq + 2 * j + 1) * CC]);
        }
#pragma unroll
        for (int kc = 0; kc < 2; kc++) {
            int kb = kc * 16;
            uint32_t bf[4][2];
#pragma unroll
            for (int nt = 0; nt < 4; nt++) {
                int n = wn * 32 + nt * 8 + r;
                bf[nt][0] = *(uint32_t*)&b_s[cur][n][kb + 2 * c];
                bf[nt][1] = *(uint32_t*)&b_s[cur][n][kb + 2 * c + 8];
            }
#pragma unroll
            for (int mt = 0; mt < 4; mt++) {
                int m = wm * 64 + mt * 16;
                uint32_t af[4];
                af[0] = *(uint32_t*)&a_s[cur][m + r][kb + 2 * c];
                af[1] = *(uint32_t*)&a_s[cur][m + r + 8][kb + 2 * c];
                af[2] = *(uint32_t*)&a_s[cur][m + r][kb + 2 * c + 8];
                af[3] = *(uint32_t*)&a_s[cur][m + r + 8][kb + 2 * c + 8];
#pragma unroll
                for (int nt = 0; nt < 4; nt++) mma_f16(acc[mt][nt], af, bf[nt]);
            }
        }
        if (more) {
            int nxt = cur ^ 1;
            uint32_t* ad = (uint32_t*)&a_s[nxt][arow][akh];
            uint32_t* bd = (uint32_t*)&b_s[nxt][bn][bkq];
#pragma unroll
            for (int j = 0; j < 8; j++) { ad[j] = pa[j]; bd[j] = pb[j]; }
            __syncthreads();
            cur = nxt;
        }
    }

    int c2 = c * 2;
    float2 bb[4];
#pragma unroll
    for (int nt = 0; nt < 4; nt++)
        bb[nt] = *(const float2*)&bo[n0 + wn * 32 + nt * 8 + c2];
#pragma unroll
    for (int mt = 0; mt < 4; mt++) {
#pragma unroll
        for (int h = 0; h < 2; h++) {
            int mm = m0 + wm * 64 + mt * 16 + r + h * 8;
            int bbx = mm / 3136, rr = mm % 3136;
            int pp = rr >> 6, px = rr & 63;
            int yy = (pp / NW) * WS + (px >> 3);
            int xq = (pp % NW) * WS + (px & 7);
            float* orow = out + (size_t)(bbx * 3136 + yy * WDIM + xq) * CC
                        + n0 + wn * 32 + c2;
#pragma unroll
            for (int nt = 0; nt < 4; nt++) {
                float4 a = acc[mt][nt];
                float2 o;
                o.x = (h ? a.z : a.x) + bb[nt].x;
                o.y = (h ? a.w : a.y) + bb[nt].y;
                *(float2*)(orow + nt * 8) = o;
            }
        }
    }
}

// ---------------------------------------------------------------------------
extern "C" void kernel_launch(void* const* d_in, const int* in_sizes, int n_in,
                              void* d_out, int out_size)
{
    const float* x      = (const float*)d_in[0];
    const float* Wqkv   = (const float*)d_in[1];
    const float* bqkv   = (const float*)d_in[2];
    const float* Wo     = (const float*)d_in[3];
    const float* bo     = (const float*)d_in[4];
    const float* lepe_w = (const float*)d_in[5];
    const float* lepe_b = (const float*)d_in[6];
    float* out = (float*)d_out;

    cudaFuncSetAttribute(attn_tc_kernel,
                         cudaFuncAttributeMaxDynamicSharedMemorySize,
                         AH_BYTES);

    // order keeps attn in the ncu capture slot (4th launch)
    gemm_qkv_f16<<<dim3(MTOT / 128, QKVW / 128), 256>>>(x, Wqkv, bqkv);
    routing_kernel<<<BB * P2, 256>>>();
    lepe_kernel<<<BB * P2 * 4, 256>>>(lepe_w, lepe_b);
    attn_tc_kernel<<<BB * P2 * NHEAD, 256, AH_BYTES>>>();
    gemm_out_f16<<<dim3(MTOT / 128, CC / 128), 256>>>(Wo, bo, out);
}